// round 8
// baseline (speedup 1.0000x reference)
#include <cuda_runtime.h>
#include <cuda_bf16.h>
#include <cstdint>

#define NN 50000
#define NNP 50048          // padded to 391*128
#define NE 800000
#define DIM 96
#define H2 192
#define NG 64
#define P1 104             // GEMM1 smem K stride (elements)
#define P2 200             // GEMM2 smem K stride (elements)

// ---------------------------------------------------------------------------
// Scratch (static device globals)
// ---------------------------------------------------------------------------
__device__ float g_h0[NNP * DIM];
__device__ float g_h1[NNP * DIM];
__device__ float g_g [NG * DIM];
__device__ __nv_bfloat16 g_w1h[3 * 192 * P1];
__device__ __nv_bfloat16 g_w1l[3 * 192 * P1];
__device__ __nv_bfloat16 g_w2h[3 * 96 * P2];
__device__ __nv_bfloat16 g_w2l[3 * 96 * P2];
// CSR structures
__device__ int g_deg   [NN];
__device__ int g_start [NN + 1];
__device__ int g_cursor[NN];
__device__ int g_ssrc  [NE];

// ---------------------------------------------------------------------------
__device__ __forceinline__ uint32_t pack2(__nv_bfloat16 a, __nv_bfloat16 b) {
    return (uint32_t)__bfloat16_as_ushort(a) | ((uint32_t)__bfloat16_as_ushort(b) << 16);
}
__device__ __forceinline__ void split_bf16(float v, __nv_bfloat16& h, __nv_bfloat16& l) {
    h = __float2bfloat16(v);
    l = __float2bfloat16(v - __bfloat162float(h));
}
__device__ __forceinline__ void mma16816(float* d, const uint32_t* a, const uint32_t* b) {
    asm volatile("mma.sync.aligned.m16n8k16.row.col.f32.bf16.bf16.f32 "
        "{%0,%1,%2,%3}, {%4,%5,%6,%7}, {%8,%9}, {%0,%1,%2,%3};"
        : "+f"(d[0]), "+f"(d[1]), "+f"(d[2]), "+f"(d[3])
        : "r"(a[0]), "r"(a[1]), "r"(a[2]), "r"(a[3]), "r"(b[0]), "r"(b[1]));
}
__device__ __forceinline__ void cp_async16(uint32_t saddr, const void* gptr) {
    asm volatile("cp.async.cg.shared.global [%0], [%1], 16;" :: "r"(saddr), "l"(gptr));
}
#define CP_COMMIT() asm volatile("cp.async.commit_group;" ::: "memory")
#define CP_WAIT(n)  asm volatile("cp.async.wait_group %0;" :: "n"(n) : "memory")

// ---------------------------------------------------------------------------
// CSR build: zero -> histogram -> scan -> reorder
// ---------------------------------------------------------------------------
__global__ void zero_deg_kernel() {
    int i = blockIdx.x * blockDim.x + threadIdx.x;
    if (i < NN) g_deg[i] = 0;
}
__global__ void hist_kernel(const int* __restrict__ ei) {
    int i = blockIdx.x * blockDim.x + threadIdx.x;
    if (i < NE) atomicAdd(&g_deg[ei[NE + i]], 1);
}
#define CHUNK 49
__global__ __launch_bounds__(1024) void scan_kernel() {
    __shared__ int csum[1024];
    int tid = threadIdx.x;
    int base = tid * CHUNK;
    int s = 0;
    for (int j = 0; j < CHUNK; j++) {
        int i = base + j;
        if (i < NN) s += g_deg[i];
    }
    csum[tid] = s;
    __syncthreads();
    for (int off = 1; off < 1024; off <<= 1) {
        int t = (tid >= off) ? csum[tid - off] : 0;
        __syncthreads();
        csum[tid] += t;
        __syncthreads();
    }
    int run = csum[tid] - s;
    for (int j = 0; j < CHUNK; j++) {
        int i = base + j;
        if (i < NN) {
            g_start[i]  = run;
            g_cursor[i] = run;
            run += g_deg[i];
        }
    }
    if (tid == 1023) g_start[NN] = csum[1023];
}
__global__ void reorder_kernel(const int* __restrict__ ei) {
    int e = blockIdx.x * blockDim.x + threadIdx.x;
    if (e < NE) {
        int dst = ei[NE + e];
        int pos = atomicAdd(&g_cursor[dst], 1);
        g_ssrc[pos] = ei[e];
    }
}

// ---------------------------------------------------------------------------
// Weight prep
// ---------------------------------------------------------------------------
__global__ void prep_w1(const float* __restrict__ W1) {
    int i = blockIdx.x * blockDim.x + threadIdx.x;
    if (i >= 3 * 192 * 96) return;
    int l = i / 18432, r = i % 18432;
    int n = r / 96, k = r % 96;
    float v = W1[(size_t)l * 96 * 192 + k * 192 + n];
    __nv_bfloat16 h, lo; split_bf16(v, h, lo);
    g_w1h[l * 192 * P1 + n * P1 + k] = h;
    g_w1l[l * 192 * P1 + n * P1 + k] = lo;
}
__global__ void prep_w2(const float* __restrict__ W2) {
    int i = blockIdx.x * blockDim.x + threadIdx.x;
    if (i >= 3 * 96 * 192) return;
    int l = i / 18432, r = i % 18432;
    int n = r / 192, k = r % 192;
    float v = W2[(size_t)l * 192 * 96 + k * 96 + n];
    __nv_bfloat16 h, lo; split_bf16(v, h, lo);
    g_w2h[l * 96 * P2 + n * P2 + k] = h;
    g_w2l[l * 96 * P2 + n * P2 + k] = lo;
}

// ---------------------------------------------------------------------------
// Fused layer: gather + GEMM1 + GEMM2, 512 threads (16 warps, 4x4 grid)
//   z[n] = (1+eps)*h[n] + sum_{CSR[n]} h[src]      (gathered into smem A)
//   h'   = relu( relu(z@W1+b1) @ W2 + b2 )
// smem layout (dynamic, 211200 B):
//   [0,768) bias1 | [768,1152) bias2 | pad
//   A hi @1280 (26624) | A lo @27904 (26624)
//   B1h @54528 (39936) | B1l @94464 (39936)
//   B2h @134400 (38400)| B2l @172800 (38400)
//   z1h @1280 (51200)  | z1l @52480 (51200)   (overlays A/B1 after gemm1)
//   sC  @1280 (51200)  fp32                    (overlays z1 after gemm2)
// ---------------------------------------------------------------------------
#define OFF_B1S  0
#define OFF_B2S  768
#define OFF_AH   1280
#define OFF_AL   27904
#define OFF_B1H  54528
#define OFF_B1L  94464
#define OFF_B2H  134400
#define OFF_B2L  172800
#define OFF_Z1H  1280
#define OFF_Z1L  52480
#define OFF_SC   1280
#define L_SMEM   211200

__global__ __launch_bounds__(512) void layer_fused(
    const float* __restrict__ hin,
    const __nv_bfloat16* __restrict__ B1h, const __nv_bfloat16* __restrict__ B1l,
    const float* __restrict__ bias1,
    const __nv_bfloat16* __restrict__ B2h, const __nv_bfloat16* __restrict__ B2l,
    const float* __restrict__ bias2,
    const float* __restrict__ eps, int lidx,
    float* __restrict__ C)
{
    extern __shared__ char sm[];
    float* b1s = (float*)(sm + OFF_B1S);
    float* b2s = (float*)(sm + OFF_B2S);
    __nv_bfloat16* sAh  = (__nv_bfloat16*)(sm + OFF_AH);
    __nv_bfloat16* sAl  = (__nv_bfloat16*)(sm + OFF_AL);
    __nv_bfloat16* sB1h = (__nv_bfloat16*)(sm + OFF_B1H);
    __nv_bfloat16* sB1l = (__nv_bfloat16*)(sm + OFF_B1L);
    __nv_bfloat16* sB2h = (__nv_bfloat16*)(sm + OFF_B2H);
    __nv_bfloat16* sB2l = (__nv_bfloat16*)(sm + OFF_B2L);
    __nv_bfloat16* z1h  = (__nv_bfloat16*)(sm + OFF_Z1H);
    __nv_bfloat16* z1l  = (__nv_bfloat16*)(sm + OFF_Z1L);
    int tid = threadIdx.x, lane = tid & 31, wid = tid >> 5;
    int row0 = blockIdx.x * 128;
    uint32_t smb = (uint32_t)__cvta_generic_to_shared(sm);

    // ---- group0: B1 + biases ----
    for (int i = tid; i < 2496; i += 512) {
        cp_async16(smb + OFF_B1H + i * 16, (const char*)B1h + i * 16);
        cp_async16(smb + OFF_B1L + i * 16, (const char*)B1l + i * 16);
    }
    if (tid < 48) cp_async16(smb + OFF_B1S + tid * 16, (const char*)bias1 + tid * 16);
    if (tid >= 64 && tid < 88) cp_async16(smb + OFF_B2S + (tid - 64) * 16, (const char*)bias2 + (tid - 64) * 16);
    CP_COMMIT();
    // ---- group1: B2 ----
    for (int i = tid; i < 2400; i += 512) {
        cp_async16(smb + OFF_B2H + i * 16, (const char*)B2h + i * 16);
        cp_async16(smb + OFF_B2L + i * 16, (const char*)B2l + i * 16);
    }
    CP_COMMIT();

    // ---- gather phase: 16 warps x 8 nodes; lane covers cols {l, l+32, l+64} ----
    {
        float sc = 1.0f + eps[lidx];
        for (int i = 0; i < 8; i++) {
            int r = wid * 8 + i;
            int n = row0 + r;
            float z0 = 0.f, z1v = 0.f, z2 = 0.f;
            if (n < NN) {
                int beg = g_start[n], end = g_start[n + 1];
                float a0=0.f,a1=0.f,a2=0.f, b0=0.f,b1=0.f,b2v=0.f;
                float c0=0.f,c1=0.f,c2=0.f, e0=0.f,e1=0.f,e2=0.f;
                int e = beg;
                for (; e + 4 <= end; e += 4) {
                    int s0 = g_ssrc[e], s1 = g_ssrc[e+1], s2 = g_ssrc[e+2], s3 = g_ssrc[e+3];
                    const float* p0 = hin + (size_t)s0 * DIM + lane;
                    const float* p1 = hin + (size_t)s1 * DIM + lane;
                    const float* p2 = hin + (size_t)s2 * DIM + lane;
                    const float* p3 = hin + (size_t)s3 * DIM + lane;
                    a0 += p0[0];  a1 += p0[32];  a2 += p0[64];
                    b0 += p1[0];  b1 += p1[32];  b2v += p1[64];
                    c0 += p2[0];  c1 += p2[32];  c2 += p2[64];
                    e0 += p3[0];  e1 += p3[32];  e2 += p3[64];
                }
                for (; e < end; e++) {
                    const float* p = hin + (size_t)g_ssrc[e] * DIM + lane;
                    a0 += p[0]; a1 += p[32]; a2 += p[64];
                }
                const float* hp = hin + (size_t)n * DIM + lane;
                z0  = fmaf(sc, hp[0],  (a0 + b0) + (c0 + e0));
                z1v = fmaf(sc, hp[32], (a1 + b1) + (c1 + e1));
                z2  = fmaf(sc, hp[64], (a2 + b2v) + (c2 + e2));
            }
            __nv_bfloat16 h0, l0, h1, l1, h2, l2;
            split_bf16(z0, h0, l0); split_bf16(z1v, h1, l1); split_bf16(z2, h2, l2);
            uint32_t off = (uint32_t)r * P1 + lane;
            sAh[off]      = h0;  sAl[off]      = l0;
            sAh[off + 32] = h1;  sAl[off + 32] = l1;
            sAh[off + 64] = h2;  sAl[off + 64] = l2;
        }
    }
    CP_WAIT(1);          // group0 (B1 + biases) landed
    __syncthreads();

    int wm = wid >> 2, wn = wid & 3;
    int arow = wm * 32 + (lane >> 2);
    int kc = (lane & 3) * 2;

    // ---- gemm1: 128x192, K=96; warp tile 32x48 ----
    {
        float d[2][6][4];
#pragma unroll
        for (int m = 0; m < 2; m++)
#pragma unroll
            for (int j = 0; j < 6; j++)
#pragma unroll
                for (int t = 0; t < 4; t++) d[m][j][t] = 0.0f;

#pragma unroll
        for (int k0 = 0; k0 < 96; k0 += 16) {
            uint32_t ah[2][4], al[2][4];
#pragma unroll
            for (int m = 0; m < 2; m++) {
                uint32_t o = (uint32_t)(arow + m * 16) * P1 + k0 + kc;
                ah[m][0] = *(uint32_t*)&sAh[o];
                ah[m][1] = *(uint32_t*)&sAh[o + 8 * P1];
                ah[m][2] = *(uint32_t*)&sAh[o + 8];
                ah[m][3] = *(uint32_t*)&sAh[o + 8 * P1 + 8];
                al[m][0] = *(uint32_t*)&sAl[o];
                al[m][1] = *(uint32_t*)&sAl[o + 8 * P1];
                al[m][2] = *(uint32_t*)&sAl[o + 8];
                al[m][3] = *(uint32_t*)&sAl[o + 8 * P1 + 8];
            }
#pragma unroll
            for (int j = 0; j < 6; j++) {
                uint32_t ob = (uint32_t)(wn * 48 + j * 8 + (lane >> 2)) * P1 + k0 + kc;
                uint32_t bh[2] = { *(uint32_t*)&sB1h[ob], *(uint32_t*)&sB1h[ob + 8] };
                uint32_t bl[2] = { *(uint32_t*)&sB1l[ob], *(uint32_t*)&sB1l[ob + 8] };
#pragma unroll
                for (int m = 0; m < 2; m++) {
                    mma16816(d[m][j], ah[m], bh);
                    mma16816(d[m][j], ah[m], bl);
                    mma16816(d[m][j], al[m], bh);
                }
            }
        }
        __syncthreads();   // done reading sA/sB1 before overwrite

        // ---- z1 = relu(d + b1) -> smem hi/lo ----
#pragma unroll
        for (int m = 0; m < 2; m++) {
            int r1 = wm * 32 + m * 16 + (lane >> 2);
#pragma unroll
            for (int j = 0; j < 6; j++) {
                int c0 = wn * 48 + j * 8 + (lane & 3) * 2;
                float v0 = fmaxf(d[m][j][0] + b1s[c0],     0.0f);
                float v1 = fmaxf(d[m][j][1] + b1s[c0 + 1], 0.0f);
                float v2 = fmaxf(d[m][j][2] + b1s[c0],     0.0f);
                float v3 = fmaxf(d[m][j][3] + b1s[c0 + 1], 0.0f);
                __nv_bfloat16 h0,l0,h1,l1,h2,l2,h3,l3;
                split_bf16(v0,h0,l0); split_bf16(v1,h1,l1);
                split_bf16(v2,h2,l2); split_bf16(v3,h3,l3);
                *(uint32_t*)&z1h[r1 * P2 + c0]       = pack2(h0, h1);
                *(uint32_t*)&z1l[r1 * P2 + c0]       = pack2(l0, l1);
                *(uint32_t*)&z1h[(r1 + 8) * P2 + c0] = pack2(h2, h3);
                *(uint32_t*)&z1l[(r1 + 8) * P2 + c0] = pack2(l2, l3);
            }
        }
    }
    CP_WAIT(0);          // B2 landed
    __syncthreads();

    // ---- gemm2: 128x96, K=192; warp tile 32x24 ----
    float d2[2][3][4];
#pragma unroll
    for (int m = 0; m < 2; m++)
#pragma unroll
        for (int j = 0; j < 3; j++)
#pragma unroll
            for (int t = 0; t < 4; t++) d2[m][j][t] = 0.0f;

#pragma unroll
    for (int k0 = 0; k0 < 192; k0 += 16) {
        uint32_t ah[2][4], al[2][4];
#pragma unroll
        for (int m = 0; m < 2; m++) {
            uint32_t o = (uint32_t)(arow + m * 16) * P2 + k0 + kc;
            ah[m][0] = *(uint32_t*)&z1h[o];
            ah[m][1] = *(uint32_t*)&z1h[o + 8 * P2];
            ah[m][2] = *(uint32_t*)&z1h[o + 8];
            ah[m][3] = *(uint32_t*)&z1h[o + 8 * P2 + 8];
            al[m][0] = *(uint32_t*)&z1l[o];
            al[m][1] = *(uint32_t*)&z1l[o + 8 * P2];
            al[m][2] = *(uint32_t*)&z1l[o + 8];
            al[m][3] = *(uint32_t*)&z1l[o + 8 * P2 + 8];
        }
#pragma unroll
        for (int j = 0; j < 3; j++) {
            uint32_t ob = (uint32_t)(wn * 24 + j * 8 + (lane >> 2)) * P2 + k0 + kc;
            uint32_t bh[2] = { *(uint32_t*)&sB2h[ob], *(uint32_t*)&sB2h[ob + 8] };
            uint32_t bl[2] = { *(uint32_t*)&sB2l[ob], *(uint32_t*)&sB2l[ob + 8] };
#pragma unroll
            for (int m = 0; m < 2; m++) {
                mma16816(d2[m][j], ah[m], bh);
                mma16816(d2[m][j], ah[m], bl);
                mma16816(d2[m][j], al[m], bh);
            }
        }
    }
    __syncthreads();   // z1 dead; reuse as sC

    float* sC = (float*)(sm + OFF_SC);               // [128][100]
#pragma unroll
    for (int m = 0; m < 2; m++) {
        int r1 = wm * 32 + m * 16 + (lane >> 2);
#pragma unroll
        for (int j = 0; j < 3; j++) {
            int c0 = wn * 24 + j * 8 + (lane & 3) * 2;
            *(float2*)&sC[r1 * 100 + c0] = make_float2(
                fmaxf(d2[m][j][0] + b2s[c0],     0.0f),
                fmaxf(d2[m][j][1] + b2s[c0 + 1], 0.0f));
            *(float2*)&sC[(r1 + 8) * 100 + c0] = make_float2(
                fmaxf(d2[m][j][2] + b2s[c0],     0.0f),
                fmaxf(d2[m][j][3] + b2s[c0 + 1], 0.0f));
        }
    }
    __syncthreads();
    float4* gC = (float4*)(C + (size_t)row0 * DIM);
    for (int i = tid; i < 3072; i += 512) {
        int r = i / 24, c = i % 24;
        gC[i] = *(float4*)&sC[r * 100 + c * 4];
    }
}

// ---------------------------------------------------------------------------
// Pool + final MLP
// ---------------------------------------------------------------------------
__global__ void zero_g_kernel() {
    int i = blockIdx.x * blockDim.x + threadIdx.x;
    if (i < NG * DIM) g_g[i] = 0.0f;
}
__global__ void pool_kernel(const float* __restrict__ h,
                            const int* __restrict__ batch) {
    int i = blockIdx.x * blockDim.x + threadIdx.x;
    if (i < NN * 24) {
        int n = i / 24, c = i % 24;
        int b = batch[n];
        float4 v = *(const float4*)&h[(size_t)n * DIM + c * 4];
        atomicAdd((float4*)&g_g[(size_t)b * DIM] + c, v);
    }
}
__global__ __launch_bounds__(256) void final_kernel(
    const float* __restrict__ fW1, const float* __restrict__ fb1,
    const float* __restrict__ fW2, const float* __restrict__ fb2,
    float* __restrict__ out)
{
    __shared__ float gs[NG * DIM];
    __shared__ float t1[NG * DIM];
    int tid = threadIdx.x;
    for (int i = tid; i < NG * DIM; i += 256) gs[i] = g_g[i];
    __syncthreads();
    for (int o = tid; o < NG * DIM; o += 256) {
        int gi = o / DIM, j = o % DIM;
        float acc = fb1[j];
#pragma unroll 8
        for (int k = 0; k < DIM; k++)
            acc = fmaf(gs[gi * DIM + k], fW1[k * DIM + j], acc);
        t1[o] = fmaxf(acc, 0.0f);
    }
    __syncthreads();
    if (tid < NG) {
        float acc = fb2[0];
#pragma unroll 8
        for (int k = 0; k < DIM; k++)
            acc = fmaf(t1[tid * DIM + k], fW2[k], acc);
        out[tid] = acc;
    }
}

// ---------------------------------------------------------------------------
extern "C" void kernel_launch(void* const* d_in, const int* in_sizes, int n_in,
                              void* d_out, int out_size) {
    const float* x     = (const float*)d_in[0];
    const int*   ei    = (const int*)d_in[1];
    const int*   batch = (const int*)d_in[2];
    const float* W1    = (const float*)d_in[3];
    const float* b1    = (const float*)d_in[4];
    const float* W2    = (const float*)d_in[5];
    const float* b2    = (const float*)d_in[6];
    const float* eps   = (const float*)d_in[7];
    const float* fW1   = (const float*)d_in[8];
    const float* fb1   = (const float*)d_in[9];
    const float* fW2   = (const float*)d_in[10];
    const float* fb2   = (const float*)d_in[11];
    float*       out   = (float*)d_out;

    static bool attr_done = false;
    if (!attr_done) {
        cudaFuncSetAttribute(layer_fused, cudaFuncAttributeMaxDynamicSharedMemorySize, L_SMEM);
        attr_done = true;
    }

    float *h0p, *h1p;
    __nv_bfloat16 *w1hp, *w1lp, *w2hp, *w2lp;
    cudaGetSymbolAddress((void**)&h0p,  g_h0);
    cudaGetSymbolAddress((void**)&h1p,  g_h1);
    cudaGetSymbolAddress((void**)&w1hp, g_w1h);
    cudaGetSymbolAddress((void**)&w1lp, g_w1l);
    cudaGetSymbolAddress((void**)&w2hp, g_w2h);
    cudaGetSymbolAddress((void**)&w2lp, g_w2l);
    float* hbufs[2] = {h0p, h1p};

    // CSR build
    zero_deg_kernel<<<(NN + 255) / 256, 256>>>();
    hist_kernel<<<(NE + 255) / 256, 256>>>(ei);
    scan_kernel<<<1, 1024>>>();
    reorder_kernel<<<(NE + 255) / 256, 256>>>(ei);

    prep_w1<<<216, 256>>>(W1);
    prep_w2<<<216, 256>>>(W2);

    const int tiles = NNP / 128;   // 391
    const float* hin = x;
    for (int l = 0; l < 3; l++) {
        float* hout = hbufs[l & 1];
        layer_fused<<<tiles, 512, L_SMEM>>>(
            hin,
            w1hp + l * 192 * P1, w1lp + l * 192 * P1, b1 + (size_t)l * H2,
            w2hp + l * 96 * P2, w2lp + l * 96 * P2, b2 + (size_t)l * DIM,
            eps, l, hout);
        hin = hout;
    }

    zero_g_kernel<<<(NG * DIM + 255) / 256, 256>>>();
    pool_kernel<<<(NN * 24 + 255) / 256, 256>>>(hin, batch);
    final_kernel<<<1, 256>>>(fW1, fb1, fW2, fb2, out);
}

// round 9
// speedup vs baseline: 1.1362x; 1.1362x over previous
#include <cuda_runtime.h>
#include <cuda_bf16.h>
#include <cstdint>

#define NN 50000
#define NNP 50048          // padded to 391*128
#define NE 800000
#define DIM 96
#define H2 192
#define NG 64
#define P1 104             // GEMM1 smem K stride (elements)
#define P2 200             // GEMM2 smem K stride (elements)

// ---------------------------------------------------------------------------
// Scratch (static device globals)
// ---------------------------------------------------------------------------
__device__ float g_z [NNP * DIM];
__device__ float g_h0[NNP * DIM];
__device__ float g_h1[NNP * DIM];
__device__ float g_g [NG * DIM];
__device__ __nv_bfloat16 g_w1h[3 * 192 * P1];
__device__ __nv_bfloat16 g_w1l[3 * 192 * P1];
__device__ __nv_bfloat16 g_w2h[3 * 96 * P2];
__device__ __nv_bfloat16 g_w2l[3 * 96 * P2];
// CSR structures
__device__ int g_deg   [NN];
__device__ int g_start [NN + 1];
__device__ int g_cursor[NN];
__device__ int g_ssrc  [NE];

// ---------------------------------------------------------------------------
__device__ __forceinline__ uint32_t pack2(__nv_bfloat16 a, __nv_bfloat16 b) {
    return (uint32_t)__bfloat16_as_ushort(a) | ((uint32_t)__bfloat16_as_ushort(b) << 16);
}
__device__ __forceinline__ void split_bf16(float v, __nv_bfloat16& h, __nv_bfloat16& l) {
    h = __float2bfloat16(v);
    l = __float2bfloat16(v - __bfloat162float(h));
}
__device__ __forceinline__ void mma16816(float* d, const uint32_t* a, const uint32_t* b) {
    asm volatile("mma.sync.aligned.m16n8k16.row.col.f32.bf16.bf16.f32 "
        "{%0,%1,%2,%3}, {%4,%5,%6,%7}, {%8,%9}, {%0,%1,%2,%3};"
        : "+f"(d[0]), "+f"(d[1]), "+f"(d[2]), "+f"(d[3])
        : "r"(a[0]), "r"(a[1]), "r"(a[2]), "r"(a[3]), "r"(b[0]), "r"(b[1]));
}
__device__ __forceinline__ void cp_async16(uint32_t saddr, const void* gptr) {
    asm volatile("cp.async.cg.shared.global [%0], [%1], 16;" :: "r"(saddr), "l"(gptr));
}
#define CP_COMMIT() asm volatile("cp.async.commit_group;" ::: "memory")
#define CP_WAIT(n)  asm volatile("cp.async.wait_group %0;" :: "n"(n) : "memory")

// ---------------------------------------------------------------------------
// CSR build: zero -> histogram -> scan -> reorder
// ---------------------------------------------------------------------------
__global__ void zero_deg_kernel() {
    int i = blockIdx.x * blockDim.x + threadIdx.x;
    if (i < NN) g_deg[i] = 0;
}
__global__ void hist_kernel(const int* __restrict__ ei) {
    int i = blockIdx.x * blockDim.x + threadIdx.x;
    if (i < NE) atomicAdd(&g_deg[ei[NE + i]], 1);
}
#define CHUNK 49
__global__ __launch_bounds__(1024) void scan_kernel() {
    __shared__ int csum[1024];
    int tid = threadIdx.x;
    int base = tid * CHUNK;
    int s = 0;
    for (int j = 0; j < CHUNK; j++) {
        int i = base + j;
        if (i < NN) s += g_deg[i];
    }
    csum[tid] = s;
    __syncthreads();
    for (int off = 1; off < 1024; off <<= 1) {
        int t = (tid >= off) ? csum[tid - off] : 0;
        __syncthreads();
        csum[tid] += t;
        __syncthreads();
    }
    int run = csum[tid] - s;
    for (int j = 0; j < CHUNK; j++) {
        int i = base + j;
        if (i < NN) {
            g_start[i]  = run;
            g_cursor[i] = run;
            run += g_deg[i];
        }
    }
    if (tid == 1023) g_start[NN] = csum[1023];
}
__global__ void reorder_kernel(const int* __restrict__ ei) {
    int e = blockIdx.x * blockDim.x + threadIdx.x;
    if (e < NE) {
        int dst = ei[NE + e];
        int pos = atomicAdd(&g_cursor[dst], 1);
        g_ssrc[pos] = ei[e];
    }
}

// ---------------------------------------------------------------------------
// Standalone gather (high occupancy): z[n] = (1+eps)*h[n] + sum_{CSR[n]} h[src]
// ---------------------------------------------------------------------------
__global__ __launch_bounds__(256) void gather_kernel(const float* __restrict__ h,
                                                     const float* __restrict__ eps, int l) {
    int wid = threadIdx.x >> 5, lane = threadIdx.x & 31;
    int n = blockIdx.x * 8 + wid;
    if (n >= NN) return;
    int beg = g_start[n], end = g_start[n + 1];
    float a0 = 0.f, a1 = 0.f, a2 = 0.f;
    float b0 = 0.f, b1 = 0.f, b2 = 0.f;
    float c0 = 0.f, c1 = 0.f, c2 = 0.f;
    float e0 = 0.f, e1 = 0.f, e2 = 0.f;
    int e = beg;
    for (; e + 4 <= end; e += 4) {
        int s0 = g_ssrc[e], s1 = g_ssrc[e + 1], s2 = g_ssrc[e + 2], s3 = g_ssrc[e + 3];
        const float* p0 = h + (size_t)s0 * DIM + lane;
        const float* p1 = h + (size_t)s1 * DIM + lane;
        const float* p2 = h + (size_t)s2 * DIM + lane;
        const float* p3 = h + (size_t)s3 * DIM + lane;
        a0 += p0[0];  a1 += p0[32];  a2 += p0[64];
        b0 += p1[0];  b1 += p1[32];  b2 += p1[64];
        c0 += p2[0];  c1 += p2[32];  c2 += p2[64];
        e0 += p3[0];  e1 += p3[32];  e2 += p3[64];
    }
    for (; e < end; e++) {
        const float* p = h + (size_t)g_ssrc[e] * DIM + lane;
        a0 += p[0]; a1 += p[32]; a2 += p[64];
    }
    float sc = 1.0f + eps[l];
    const float* hp = h + (size_t)n * DIM + lane;
    float* zp = g_z + (size_t)n * DIM + lane;
    zp[0]  = fmaf(sc, hp[0],  (a0 + b0) + (c0 + e0));
    zp[32] = fmaf(sc, hp[32], (a1 + b1) + (c1 + e1));
    zp[64] = fmaf(sc, hp[64], (a2 + b2) + (c2 + e2));
}

// ---------------------------------------------------------------------------
// Weight prep
// ---------------------------------------------------------------------------
__global__ void prep_w1(const float* __restrict__ W1) {
    int i = blockIdx.x * blockDim.x + threadIdx.x;
    if (i >= 3 * 192 * 96) return;
    int l = i / 18432, r = i % 18432;
    int n = r / 96, k = r % 96;
    float v = W1[(size_t)l * 96 * 192 + k * 192 + n];
    __nv_bfloat16 h, lo; split_bf16(v, h, lo);
    g_w1h[l * 192 * P1 + n * P1 + k] = h;
    g_w1l[l * 192 * P1 + n * P1 + k] = lo;
}
__global__ void prep_w2(const float* __restrict__ W2) {
    int i = blockIdx.x * blockDim.x + threadIdx.x;
    if (i >= 3 * 96 * 192) return;
    int l = i / 18432, r = i % 18432;
    int n = r / 192, k = r % 192;
    float v = W2[(size_t)l * 192 * 96 + k * 96 + n];
    __nv_bfloat16 h, lo; split_bf16(v, h, lo);
    g_w2h[l * 96 * P2 + n * P2 + k] = h;
    g_w2l[l * 96 * P2 + n * P2 + k] = lo;
}

// ---------------------------------------------------------------------------
// Fused layer (256 threads, 8 warps 4x2): h' = relu(relu(z@W1+b1)@W2+b2)
// cp.async: group0 = B1+biases (gemm1 gate), group1 = B2 (gemm2 gate).
// do_pool: last layer pools sC into g_g instead of writing h'.
// ---------------------------------------------------------------------------
#define OFF_B1S  0
#define OFF_B2S  768
#define OFF_AH   1280
#define OFF_AL   27904
#define OFF_B1H  54528
#define OFF_B1L  94464
#define OFF_B2H  134400
#define OFF_B2L  172800
#define OFF_Z1H  1280
#define OFF_Z1L  52480
#define OFF_SC   1280
#define L_SMEM   211200

__global__ __launch_bounds__(256) void layer_fused(
    const float* __restrict__ A,
    const __nv_bfloat16* __restrict__ B1h, const __nv_bfloat16* __restrict__ B1l,
    const float* __restrict__ bias1,
    const __nv_bfloat16* __restrict__ B2h, const __nv_bfloat16* __restrict__ B2l,
    const float* __restrict__ bias2, float* __restrict__ C,
    const int* __restrict__ batch, int do_pool)
{
    extern __shared__ char sm[];
    float* b1s = (float*)(sm + OFF_B1S);
    float* b2s = (float*)(sm + OFF_B2S);
    __nv_bfloat16* sAh  = (__nv_bfloat16*)(sm + OFF_AH);
    __nv_bfloat16* sAl  = (__nv_bfloat16*)(sm + OFF_AL);
    __nv_bfloat16* sB1h = (__nv_bfloat16*)(sm + OFF_B1H);
    __nv_bfloat16* sB1l = (__nv_bfloat16*)(sm + OFF_B1L);
    __nv_bfloat16* sB2h = (__nv_bfloat16*)(sm + OFF_B2H);
    __nv_bfloat16* sB2l = (__nv_bfloat16*)(sm + OFF_B2L);
    __nv_bfloat16* z1h  = (__nv_bfloat16*)(sm + OFF_Z1H);
    __nv_bfloat16* z1l  = (__nv_bfloat16*)(sm + OFF_Z1L);
    int tid = threadIdx.x, lane = tid & 31, wid = tid >> 5;
    int row0 = blockIdx.x * 128;
    uint32_t smb = (uint32_t)__cvta_generic_to_shared(sm);

    // group0: B1 + biases (gemm1 gate)
    for (int i = tid; i < 2496; i += 256) {
        cp_async16(smb + OFF_B1H + i * 16, (const char*)B1h + i * 16);
        cp_async16(smb + OFF_B1L + i * 16, (const char*)B1l + i * 16);
    }
    if (tid < 48) cp_async16(smb + OFF_B1S + tid * 16, (const char*)bias1 + tid * 16);
    if (tid >= 64 && tid < 88)
        cp_async16(smb + OFF_B2S + (tid - 64) * 16, (const char*)bias2 + (tid - 64) * 16);
    CP_COMMIT();
    // group1: B2 (gemm2 gate)
    for (int i = tid; i < 2400; i += 256) {
        cp_async16(smb + OFF_B2H + i * 16, (const char*)B2h + i * 16);
        cp_async16(smb + OFF_B2L + i * 16, (const char*)B2l + i * 16);
    }
    CP_COMMIT();

    // A: load fp32, split hi/lo, store to smem (overlaps with cp.async groups)
    const float4* gA = (const float4*)(A + (size_t)row0 * DIM);
    for (int i = tid; i < 3072; i += 256) {
        int r = i / 24, c = i % 24;
        float4 v = gA[i];
        __nv_bfloat16 h0,l0,h1,l1,h2,l2,h3,l3;
        split_bf16(v.x,h0,l0); split_bf16(v.y,h1,l1);
        split_bf16(v.z,h2,l2); split_bf16(v.w,h3,l3);
        uint32_t off = r * P1 + c * 4;
        *(uint2*)&sAh[off] = make_uint2(pack2(h0,h1), pack2(h2,h3));
        *(uint2*)&sAl[off] = make_uint2(pack2(l0,l1), pack2(l2,l3));
    }
    CP_WAIT(1);
    __syncthreads();

    int wm = wid >> 1, wn = wid & 1;
    int arow = wm * 32 + (lane >> 2);
    int kc = (lane & 3) * 2;

    // ---- gemm1: 128x192, K=96; warp tile 32x96 ----
    {
        float d[2][12][4];
#pragma unroll
        for (int m = 0; m < 2; m++)
#pragma unroll
            for (int j = 0; j < 12; j++)
#pragma unroll
                for (int t = 0; t < 4; t++) d[m][j][t] = 0.0f;

#pragma unroll
        for (int k0 = 0; k0 < 96; k0 += 16) {
            uint32_t ah[2][4], al[2][4];
#pragma unroll
            for (int m = 0; m < 2; m++) {
                uint32_t o = (uint32_t)(arow + m * 16) * P1 + k0 + kc;
                ah[m][0] = *(uint32_t*)&sAh[o];
                ah[m][1] = *(uint32_t*)&sAh[o + 8 * P1];
                ah[m][2] = *(uint32_t*)&sAh[o + 8];
                ah[m][3] = *(uint32_t*)&sAh[o + 8 * P1 + 8];
                al[m][0] = *(uint32_t*)&sAl[o];
                al[m][1] = *(uint32_t*)&sAl[o + 8 * P1];
                al[m][2] = *(uint32_t*)&sAl[o + 8];
                al[m][3] = *(uint32_t*)&sAl[o + 8 * P1 + 8];
            }
#pragma unroll
            for (int j = 0; j < 12; j++) {
                uint32_t ob = (uint32_t)(wn * 96 + j * 8 + (lane >> 2)) * P1 + k0 + kc;
                uint32_t bh[2] = { *(uint32_t*)&sB1h[ob], *(uint32_t*)&sB1h[ob + 8] };
                uint32_t bl[2] = { *(uint32_t*)&sB1l[ob], *(uint32_t*)&sB1l[ob + 8] };
#pragma unroll
                for (int m = 0; m < 2; m++) {
                    mma16816(d[m][j], ah[m], bh);
                    mma16816(d[m][j], ah[m], bl);
                    mma16816(d[m][j], al[m], bh);
                }
            }
        }
        __syncthreads();

#pragma unroll
        for (int m = 0; m < 2; m++) {
            int r1 = wm * 32 + m * 16 + (lane >> 2);
#pragma unroll
            for (int j = 0; j < 12; j++) {
                int c0 = wn * 96 + j * 8 + (lane & 3) * 2;
                float v0 = fmaxf(d[m][j][0] + b1s[c0],     0.0f);
                float v1 = fmaxf(d[m][j][1] + b1s[c0 + 1], 0.0f);
                float v2 = fmaxf(d[m][j][2] + b1s[c0],     0.0f);
                float v3 = fmaxf(d[m][j][3] + b1s[c0 + 1], 0.0f);
                __nv_bfloat16 h0,l0,h1,l1,h2,l2,h3,l3;
                split_bf16(v0,h0,l0); split_bf16(v1,h1,l1);
                split_bf16(v2,h2,l2); split_bf16(v3,h3,l3);
                *(uint32_t*)&z1h[r1 * P2 + c0]       = pack2(h0, h1);
                *(uint32_t*)&z1l[r1 * P2 + c0]       = pack2(l0, l1);
                *(uint32_t*)&z1h[(r1 + 8) * P2 + c0] = pack2(h2, h3);
                *(uint32_t*)&z1l[(r1 + 8) * P2 + c0] = pack2(l2, l3);
            }
        }
    }
    CP_WAIT(0);
    __syncthreads();

    // ---- gemm2: 128x96, K=192; warp tile 32x48 ----
    float d2[2][6][4];
#pragma unroll
    for (int m = 0; m < 2; m++)
#pragma unroll
        for (int j = 0; j < 6; j++)
#pragma unroll
            for (int t = 0; t < 4; t++) d2[m][j][t] = 0.0f;

#pragma unroll
    for (int k0 = 0; k0 < 192; k0 += 16) {
        uint32_t ah[2][4], al[2][4];
#pragma unroll
        for (int m = 0; m < 2; m++) {
            uint32_t o = (uint32_t)(arow + m * 16) * P2 + k0 + kc;
            ah[m][0] = *(uint32_t*)&z1h[o];
            ah[m][1] = *(uint32_t*)&z1h[o + 8 * P2];
            ah[m][2] = *(uint32_t*)&z1h[o + 8];
            ah[m][3] = *(uint32_t*)&z1h[o + 8 * P2 + 8];
            al[m][0] = *(uint32_t*)&z1l[o];
            al[m][1] = *(uint32_t*)&z1l[o + 8 * P2];
            al[m][2] = *(uint32_t*)&z1l[o + 8];
            al[m][3] = *(uint32_t*)&z1l[o + 8 * P2 + 8];
        }
#pragma unroll
        for (int j = 0; j < 6; j++) {
            uint32_t ob = (uint32_t)(wn * 48 + j * 8 + (lane >> 2)) * P2 + k0 + kc;
            uint32_t bh[2] = { *(uint32_t*)&sB2h[ob], *(uint32_t*)&sB2h[ob + 8] };
            uint32_t bl[2] = { *(uint32_t*)&sB2l[ob], *(uint32_t*)&sB2l[ob + 8] };
#pragma unroll
            for (int m = 0; m < 2; m++) {
                mma16816(d2[m][j], ah[m], bh);
                mma16816(d2[m][j], ah[m], bl);
                mma16816(d2[m][j], al[m], bh);
            }
        }
    }
    __syncthreads();   // z1 dead; reuse as sC

    float* sC = (float*)(sm + OFF_SC);               // [128][100]
#pragma unroll
    for (int m = 0; m < 2; m++) {
        int r1 = wm * 32 + m * 16 + (lane >> 2);
#pragma unroll
        for (int j = 0; j < 6; j++) {
            int c0 = wn * 48 + j * 8 + (lane & 3) * 2;
            *(float2*)&sC[r1 * 100 + c0] = make_float2(
                fmaxf(d2[m][j][0] + b2s[c0],     0.0f),
                fmaxf(d2[m][j][1] + b2s[c0 + 1], 0.0f));
            *(float2*)&sC[(r1 + 8) * 100 + c0] = make_float2(
                fmaxf(d2[m][j][2] + b2s[c0],     0.0f),
                fmaxf(d2[m][j][3] + b2s[c0 + 1], 0.0f));
        }
    }
    __syncthreads();

    if (!do_pool) {
        float4* gC = (float4*)(C + (size_t)row0 * DIM);
        for (int i = tid; i < 3072; i += 256) {
            int r = i / 24, c = i % 24;
            gC[i] = *(float4*)&sC[r * 100 + c * 4];
        }
    } else {
        // last layer: pool directly into g_g (g_g pre-zeroed)
        for (int i = tid; i < 3072; i += 256) {
            int r = i / 24, c = i % 24;
            int n = row0 + r;
            if (n < NN) {
                float4 v = *(float4*)&sC[r * 100 + c * 4];
                atomicAdd((float4*)&g_g[(size_t)batch[n] * DIM] + c, v);
            }
        }
    }
}

// ---------------------------------------------------------------------------
// Pool init + final MLP
// ---------------------------------------------------------------------------
__global__ void zero_g_kernel() {
    int i = blockIdx.x * blockDim.x + threadIdx.x;
    if (i < NG * DIM) g_g[i] = 0.0f;
}
__global__ __launch_bounds__(256) void final_kernel(
    const float* __restrict__ fW1, const float* __restrict__ fb1,
    const float* __restrict__ fW2, const float* __restrict__ fb2,
    float* __restrict__ out)
{
    __shared__ float gs[NG * DIM];
    __shared__ float t1[NG * DIM];
    int tid = threadIdx.x;
    for (int i = tid; i < NG * DIM; i += 256) gs[i] = g_g[i];
    __syncthreads();
    for (int o = tid; o < NG * DIM; o += 256) {
        int gi = o / DIM, j = o % DIM;
        float acc = fb1[j];
#pragma unroll 8
        for (int k = 0; k < DIM; k++)
            acc = fmaf(gs[gi * DIM + k], fW1[k * DIM + j], acc);
        t1[o] = fmaxf(acc, 0.0f);
    }
    __syncthreads();
    if (tid < NG) {
        float acc = fb2[0];
#pragma unroll 8
        for (int k = 0; k < DIM; k++)
            acc = fmaf(t1[tid * DIM + k], fW2[k], acc);
        out[tid] = acc;
    }
}

// ---------------------------------------------------------------------------
extern "C" void kernel_launch(void* const* d_in, const int* in_sizes, int n_in,
                              void* d_out, int out_size) {
    const float* x     = (const float*)d_in[0];
    const int*   ei    = (const int*)d_in[1];
    const int*   batch = (const int*)d_in[2];
    const float* W1    = (const float*)d_in[3];
    const float* b1    = (const float*)d_in[4];
    const float* W2    = (const float*)d_in[5];
    const float* b2    = (const float*)d_in[6];
    const float* eps   = (const float*)d_in[7];
    const float* fW1   = (const float*)d_in[8];
    const float* fb1   = (const float*)d_in[9];
    const float* fW2   = (const float*)d_in[10];
    const float* fb2   = (const float*)d_in[11];
    float*       out   = (float*)d_out;

    static bool attr_done = false;
    if (!attr_done) {
        cudaFuncSetAttribute(layer_fused, cudaFuncAttributeMaxDynamicSharedMemorySize, L_SMEM);
        attr_done = true;
    }

    float *zp, *h0p, *h1p;
    __nv_bfloat16 *w1hp, *w1lp, *w2hp, *w2lp;
    cudaGetSymbolAddress((void**)&zp,   g_z);
    cudaGetSymbolAddress((void**)&h0p,  g_h0);
    cudaGetSymbolAddress((void**)&h1p,  g_h1);
    cudaGetSymbolAddress((void**)&w1hp, g_w1h);
    cudaGetSymbolAddress((void**)&w1lp, g_w1l);
    cudaGetSymbolAddress((void**)&w2hp, g_w2h);
    cudaGetSymbolAddress((void**)&w2lp, g_w2l);
    float* hbufs[2] = {h0p, h1p};

    // CSR build + pool init + weight prep (front of graph)
    zero_deg_kernel<<<(NN + 255) / 256, 256>>>();
    hist_kernel<<<(NE + 255) / 256, 256>>>(ei);
    scan_kernel<<<1, 1024>>>();
    reorder_kernel<<<(NE + 255) / 256, 256>>>(ei);
    zero_g_kernel<<<(NG * DIM + 255) / 256, 256>>>();
    prep_w1<<<216, 256>>>(W1);
    prep_w2<<<216, 256>>>(W2);

    const int tiles = NNP / 128;   // 391
    const float* hin = x;
    for (int l = 0; l < 3; l++) {
        gather_kernel<<<(NN + 7) / 8, 256>>>(hin, eps, l);
        float* hout = hbufs[l & 1];
        int do_pool = (l == 2);
        layer_fused<<<tiles, 256, L_SMEM>>>(
            zp, w1hp + l * 192 * P1, w1lp + l * 192 * P1, b1 + (size_t)l * H2,
            w2hp + l * 96 * P2, w2lp + l * 96 * P2, b2 + (size_t)l * DIM,
            hout, batch, do_pool);
        hin = hout;
    }

    final_kernel<<<1, 256>>>(fW1, fb1, fW2, fb2, out);
}

// round 10
// speedup vs baseline: 1.1772x; 1.0361x over previous
#include <cuda_runtime.h>
#include <cuda_bf16.h>
#include <cstdint>

#define NN 50000
#define NNP 50048          // padded to 391*128
#define NE 800000
#define DIM 96
#define H2 192
#define NG 64
#define P1 104             // GEMM1 smem K stride (elements)
#define P2 200             // GEMM2 smem K stride (elements)

// ---------------------------------------------------------------------------
// Scratch (static device globals)
// ---------------------------------------------------------------------------
__device__ float g_z [NNP * DIM];
__device__ float g_h0[NNP * DIM];
__device__ float g_h1[NNP * DIM];
__device__ float g_g [NG * DIM];
__device__ __nv_bfloat16 g_w1h[3 * 192 * P1];
__device__ __nv_bfloat16 g_w1l[3 * 192 * P1];
__device__ __nv_bfloat16 g_w2h[3 * 96 * P2];
__device__ __nv_bfloat16 g_w2l[3 * 96 * P2];
// CSR structures
__device__ int g_deg   [NN];
__device__ int g_start [NN + 1];
__device__ int g_cursor[NN];
__device__ int g_ssrc  [NE];

// ---------------------------------------------------------------------------
__device__ __forceinline__ uint32_t pack2(__nv_bfloat16 a, __nv_bfloat16 b) {
    return (uint32_t)__bfloat16_as_ushort(a) | ((uint32_t)__bfloat16_as_ushort(b) << 16);
}
__device__ __forceinline__ void split_bf16(float v, __nv_bfloat16& h, __nv_bfloat16& l) {
    h = __float2bfloat16(v);
    l = __float2bfloat16(v - __bfloat162float(h));
}
__device__ __forceinline__ void mma16816(float* d, const uint32_t* a, const uint32_t* b) {
    asm volatile("mma.sync.aligned.m16n8k16.row.col.f32.bf16.bf16.f32 "
        "{%0,%1,%2,%3}, {%4,%5,%6,%7}, {%8,%9}, {%0,%1,%2,%3};"
        : "+f"(d[0]), "+f"(d[1]), "+f"(d[2]), "+f"(d[3])
        : "r"(a[0]), "r"(a[1]), "r"(a[2]), "r"(a[3]), "r"(b[0]), "r"(b[1]));
}
__device__ __forceinline__ void cp_async16(uint32_t saddr, const void* gptr) {
    asm volatile("cp.async.cg.shared.global [%0], [%1], 16;" :: "r"(saddr), "l"(gptr));
}
#define CP_COMMIT() asm volatile("cp.async.commit_group;" ::: "memory")
#define CP_WAIT(n)  asm volatile("cp.async.wait_group %0;" :: "n"(n) : "memory")

// ---------------------------------------------------------------------------
// CSR build: zero -> histogram -> scan -> reorder
// ---------------------------------------------------------------------------
__global__ void zero_deg_kernel() {
    int i = blockIdx.x * blockDim.x + threadIdx.x;
    if (i < NN) g_deg[i] = 0;
}
__global__ void hist_kernel(const int* __restrict__ ei) {
    int i = blockIdx.x * blockDim.x + threadIdx.x;
    if (i < NE) atomicAdd(&g_deg[ei[NE + i]], 1);
}
#define CHUNK 49
__global__ __launch_bounds__(1024) void scan_kernel() {
    __shared__ int csum[1024];
    int tid = threadIdx.x;
    int base = tid * CHUNK;
    int s = 0;
    for (int j = 0; j < CHUNK; j++) {
        int i = base + j;
        if (i < NN) s += g_deg[i];
    }
    csum[tid] = s;
    __syncthreads();
    for (int off = 1; off < 1024; off <<= 1) {
        int t = (tid >= off) ? csum[tid - off] : 0;
        __syncthreads();
        csum[tid] += t;
        __syncthreads();
    }
    int run = csum[tid] - s;
    for (int j = 0; j < CHUNK; j++) {
        int i = base + j;
        if (i < NN) {
            g_start[i]  = run;
            g_cursor[i] = run;
            run += g_deg[i];
        }
    }
    if (tid == 1023) g_start[NN] = csum[1023];
}
__global__ void reorder_kernel(const int* __restrict__ ei) {
    int e = blockIdx.x * blockDim.x + threadIdx.x;
    if (e < NE) {
        int dst = ei[NE + e];
        int pos = atomicAdd(&g_cursor[dst], 1);
        g_ssrc[pos] = ei[e];
    }
}

// ---------------------------------------------------------------------------
// Standalone gather (high occupancy): z[n] = (1+eps)*h[n] + sum_{CSR[n]} h[src]
// ---------------------------------------------------------------------------
__global__ __launch_bounds__(256) void gather_kernel(const float* __restrict__ h,
                                                     const float* __restrict__ eps, int l) {
    int wid = threadIdx.x >> 5, lane = threadIdx.x & 31;
    int n = blockIdx.x * 8 + wid;
    if (n >= NN) return;
    int beg = g_start[n], end = g_start[n + 1];
    float a0 = 0.f, a1 = 0.f, a2 = 0.f;
    float b0 = 0.f, b1 = 0.f, b2 = 0.f;
    float c0 = 0.f, c1 = 0.f, c2 = 0.f;
    float e0 = 0.f, e1 = 0.f, e2 = 0.f;
    int e = beg;
    for (; e + 4 <= end; e += 4) {
        int s0 = g_ssrc[e], s1 = g_ssrc[e + 1], s2 = g_ssrc[e + 2], s3 = g_ssrc[e + 3];
        const float* p0 = h + (size_t)s0 * DIM + lane;
        const float* p1 = h + (size_t)s1 * DIM + lane;
        const float* p2 = h + (size_t)s2 * DIM + lane;
        const float* p3 = h + (size_t)s3 * DIM + lane;
        a0 += p0[0];  a1 += p0[32];  a2 += p0[64];
        b0 += p1[0];  b1 += p1[32];  b2 += p1[64];
        c0 += p2[0];  c1 += p2[32];  c2 += p2[64];
        e0 += p3[0];  e1 += p3[32];  e2 += p3[64];
    }
    for (; e < end; e++) {
        const float* p = h + (size_t)g_ssrc[e] * DIM + lane;
        a0 += p[0]; a1 += p[32]; a2 += p[64];
    }
    float sc = 1.0f + eps[l];
    const float* hp = h + (size_t)n * DIM + lane;
    float* zp = g_z + (size_t)n * DIM + lane;
    zp[0]  = fmaf(sc, hp[0],  (a0 + b0) + (c0 + e0));
    zp[32] = fmaf(sc, hp[32], (a1 + b1) + (c1 + e1));
    zp[64] = fmaf(sc, hp[64], (a2 + b2) + (c2 + e2));
}

// ---------------------------------------------------------------------------
// Weight prep
// ---------------------------------------------------------------------------
__global__ void prep_w1(const float* __restrict__ W1) {
    int i = blockIdx.x * blockDim.x + threadIdx.x;
    if (i >= 3 * 192 * 96) return;
    int l = i / 18432, r = i % 18432;
    int n = r / 96, k = r % 96;
    float v = W1[(size_t)l * 96 * 192 + k * 192 + n];
    __nv_bfloat16 h, lo; split_bf16(v, h, lo);
    g_w1h[l * 192 * P1 + n * P1 + k] = h;
    g_w1l[l * 192 * P1 + n * P1 + k] = lo;
}
__global__ void prep_w2(const float* __restrict__ W2) {
    int i = blockIdx.x * blockDim.x + threadIdx.x;
    if (i >= 3 * 96 * 192) return;
    int l = i / 18432, r = i % 18432;
    int n = r / 192, k = r % 192;
    float v = W2[(size_t)l * 192 * 96 + k * 96 + n];
    __nv_bfloat16 h, lo; split_bf16(v, h, lo);
    g_w2h[l * 96 * P2 + n * P2 + k] = h;
    g_w2l[l * 96 * P2 + n * P2 + k] = lo;
}

// ---------------------------------------------------------------------------
// Fused layer (512 threads, 16 warps 4x4): h' = relu(relu(z@W1+b1)@W2+b2)
// cp.async: group0 = B1+biases (gemm1 gate), group1 = B2 (gemm2 gate).
// do_pool: last layer pools sC into g_g instead of writing h'.
// ---------------------------------------------------------------------------
#define OFF_B1S  0
#define OFF_B2S  768
#define OFF_AH   1280
#define OFF_AL   27904
#define OFF_B1H  54528
#define OFF_B1L  94464
#define OFF_B2H  134400
#define OFF_B2L  172800
#define OFF_Z1H  1280
#define OFF_Z1L  52480
#define OFF_SC   1280
#define L_SMEM   211200

__global__ __launch_bounds__(512) void layer_fused(
    const float* __restrict__ A,
    const __nv_bfloat16* __restrict__ B1h, const __nv_bfloat16* __restrict__ B1l,
    const float* __restrict__ bias1,
    const __nv_bfloat16* __restrict__ B2h, const __nv_bfloat16* __restrict__ B2l,
    const float* __restrict__ bias2, float* __restrict__ C,
    const int* __restrict__ batch, int do_pool)
{
    extern __shared__ char sm[];
    float* b1s = (float*)(sm + OFF_B1S);
    float* b2s = (float*)(sm + OFF_B2S);
    __nv_bfloat16* sAh  = (__nv_bfloat16*)(sm + OFF_AH);
    __nv_bfloat16* sAl  = (__nv_bfloat16*)(sm + OFF_AL);
    __nv_bfloat16* sB1h = (__nv_bfloat16*)(sm + OFF_B1H);
    __nv_bfloat16* sB1l = (__nv_bfloat16*)(sm + OFF_B1L);
    __nv_bfloat16* sB2h = (__nv_bfloat16*)(sm + OFF_B2H);
    __nv_bfloat16* sB2l = (__nv_bfloat16*)(sm + OFF_B2L);
    __nv_bfloat16* z1h  = (__nv_bfloat16*)(sm + OFF_Z1H);
    __nv_bfloat16* z1l  = (__nv_bfloat16*)(sm + OFF_Z1L);
    int tid = threadIdx.x, lane = tid & 31, wid = tid >> 5;
    int row0 = blockIdx.x * 128;
    uint32_t smb = (uint32_t)__cvta_generic_to_shared(sm);

    // group0: B1 + biases (gemm1 gate)
    for (int i = tid; i < 2496; i += 512) {
        cp_async16(smb + OFF_B1H + i * 16, (const char*)B1h + i * 16);
        cp_async16(smb + OFF_B1L + i * 16, (const char*)B1l + i * 16);
    }
    if (tid < 48) cp_async16(smb + OFF_B1S + tid * 16, (const char*)bias1 + tid * 16);
    if (tid >= 64 && tid < 88)
        cp_async16(smb + OFF_B2S + (tid - 64) * 16, (const char*)bias2 + (tid - 64) * 16);
    CP_COMMIT();
    // group1: B2 (gemm2 gate)
    for (int i = tid; i < 2400; i += 512) {
        cp_async16(smb + OFF_B2H + i * 16, (const char*)B2h + i * 16);
        cp_async16(smb + OFF_B2L + i * 16, (const char*)B2l + i * 16);
    }
    CP_COMMIT();

    // A: load fp32, split hi/lo, store to smem (overlaps with cp.async groups)
    const float4* gA = (const float4*)(A + (size_t)row0 * DIM);
    for (int i = tid; i < 3072; i += 512) {
        int r = i / 24, c = i % 24;
        float4 v = gA[i];
        __nv_bfloat16 h0,l0,h1,l1,h2,l2,h3,l3;
        split_bf16(v.x,h0,l0); split_bf16(v.y,h1,l1);
        split_bf16(v.z,h2,l2); split_bf16(v.w,h3,l3);
        uint32_t off = r * P1 + c * 4;
        *(uint2*)&sAh[off] = make_uint2(pack2(h0,h1), pack2(h2,h3));
        *(uint2*)&sAl[off] = make_uint2(pack2(l0,l1), pack2(l2,l3));
    }
    CP_WAIT(1);
    __syncthreads();

    int wm = wid >> 2, wn = wid & 3;         // 4x4 warp grid
    int arow = wm * 32 + (lane >> 2);
    int kc = (lane & 3) * 2;

    // ---- gemm1: 128x192, K=96; warp tile 32x48 ----
    {
        float d[2][6][4];
#pragma unroll
        for (int m = 0; m < 2; m++)
#pragma unroll
            for (int j = 0; j < 6; j++)
#pragma unroll
                for (int t = 0; t < 4; t++) d[m][j][t] = 0.0f;

#pragma unroll
        for (int k0 = 0; k0 < 96; k0 += 16) {
            uint32_t ah[2][4], al[2][4];
#pragma unroll
            for (int m = 0; m < 2; m++) {
                uint32_t o = (uint32_t)(arow + m * 16) * P1 + k0 + kc;
                ah[m][0] = *(uint32_t*)&sAh[o];
                ah[m][1] = *(uint32_t*)&sAh[o + 8 * P1];
                ah[m][2] = *(uint32_t*)&sAh[o + 8];
                ah[m][3] = *(uint32_t*)&sAh[o + 8 * P1 + 8];
                al[m][0] = *(uint32_t*)&sAl[o];
                al[m][1] = *(uint32_t*)&sAl[o + 8 * P1];
                al[m][2] = *(uint32_t*)&sAl[o + 8];
                al[m][3] = *(uint32_t*)&sAl[o + 8 * P1 + 8];
            }
#pragma unroll
            for (int j = 0; j < 6; j++) {
                uint32_t ob = (uint32_t)(wn * 48 + j * 8 + (lane >> 2)) * P1 + k0 + kc;
                uint32_t bh[2] = { *(uint32_t*)&sB1h[ob], *(uint32_t*)&sB1h[ob + 8] };
                uint32_t bl[2] = { *(uint32_t*)&sB1l[ob], *(uint32_t*)&sB1l[ob + 8] };
#pragma unroll
                for (int m = 0; m < 2; m++) {
                    mma16816(d[m][j], ah[m], bh);
                    mma16816(d[m][j], ah[m], bl);
                    mma16816(d[m][j], al[m], bh);
                }
            }
        }
        __syncthreads();

#pragma unroll
        for (int m = 0; m < 2; m++) {
            int r1 = wm * 32 + m * 16 + (lane >> 2);
#pragma unroll
            for (int j = 0; j < 6; j++) {
                int c0 = wn * 48 + j * 8 + (lane & 3) * 2;
                float v0 = fmaxf(d[m][j][0] + b1s[c0],     0.0f);
                float v1 = fmaxf(d[m][j][1] + b1s[c0 + 1], 0.0f);
                float v2 = fmaxf(d[m][j][2] + b1s[c0],     0.0f);
                float v3 = fmaxf(d[m][j][3] + b1s[c0 + 1], 0.0f);
                __nv_bfloat16 h0,l0,h1,l1,h2,l2,h3,l3;
                split_bf16(v0,h0,l0); split_bf16(v1,h1,l1);
                split_bf16(v2,h2,l2); split_bf16(v3,h3,l3);
                *(uint32_t*)&z1h[r1 * P2 + c0]       = pack2(h0, h1);
                *(uint32_t*)&z1l[r1 * P2 + c0]       = pack2(l0, l1);
                *(uint32_t*)&z1h[(r1 + 8) * P2 + c0] = pack2(h2, h3);
                *(uint32_t*)&z1l[(r1 + 8) * P2 + c0] = pack2(l2, l3);
            }
        }
    }
    CP_WAIT(0);
    __syncthreads();

    // ---- gemm2: 128x96, K=192; warp tile 32x24 ----
    float d2[2][3][4];
#pragma unroll
    for (int m = 0; m < 2; m++)
#pragma unroll
        for (int j = 0; j < 3; j++)
#pragma unroll
            for (int t = 0; t < 4; t++) d2[m][j][t] = 0.0f;

#pragma unroll
    for (int k0 = 0; k0 < 192; k0 += 16) {
        uint32_t ah[2][4], al[2][4];
#pragma unroll
        for (int m = 0; m < 2; m++) {
            uint32_t o = (uint32_t)(arow + m * 16) * P2 + k0 + kc;
            ah[m][0] = *(uint32_t*)&z1h[o];
            ah[m][1] = *(uint32_t*)&z1h[o + 8 * P2];
            ah[m][2] = *(uint32_t*)&z1h[o + 8];
            ah[m][3] = *(uint32_t*)&z1h[o + 8 * P2 + 8];
            al[m][0] = *(uint32_t*)&z1l[o];
            al[m][1] = *(uint32_t*)&z1l[o + 8 * P2];
            al[m][2] = *(uint32_t*)&z1l[o + 8];
            al[m][3] = *(uint32_t*)&z1l[o + 8 * P2 + 8];
        }
#pragma unroll
        for (int j = 0; j < 3; j++) {
            uint32_t ob = (uint32_t)(wn * 24 + j * 8 + (lane >> 2)) * P2 + k0 + kc;
            uint32_t bh[2] = { *(uint32_t*)&sB2h[ob], *(uint32_t*)&sB2h[ob + 8] };
            uint32_t bl[2] = { *(uint32_t*)&sB2l[ob], *(uint32_t*)&sB2l[ob + 8] };
#pragma unroll
            for (int m = 0; m < 2; m++) {
                mma16816(d2[m][j], ah[m], bh);
                mma16816(d2[m][j], ah[m], bl);
                mma16816(d2[m][j], al[m], bh);
            }
        }
    }
    __syncthreads();   // z1 dead; reuse as sC

    float* sC = (float*)(sm + OFF_SC);               // [128][100]
#pragma unroll
    for (int m = 0; m < 2; m++) {
        int r1 = wm * 32 + m * 16 + (lane >> 2);
#pragma unroll
        for (int j = 0; j < 3; j++) {
            int c0 = wn * 24 + j * 8 + (lane & 3) * 2;
            *(float2*)&sC[r1 * 100 + c0] = make_float2(
                fmaxf(d2[m][j][0] + b2s[c0],     0.0f),
                fmaxf(d2[m][j][1] + b2s[c0 + 1], 0.0f));
            *(float2*)&sC[(r1 + 8) * 100 + c0] = make_float2(
                fmaxf(d2[m][j][2] + b2s[c0],     0.0f),
                fmaxf(d2[m][j][3] + b2s[c0 + 1], 0.0f));
        }
    }
    __syncthreads();

    if (!do_pool) {
        float4* gC = (float4*)(C + (size_t)row0 * DIM);
        for (int i = tid; i < 3072; i += 512) {
            int r = i / 24, c = i % 24;
            gC[i] = *(float4*)&sC[r * 100 + c * 4];
        }
    } else {
        // last layer: pool directly into g_g (g_g pre-zeroed)
        for (int i = tid; i < 3072; i += 512) {
            int r = i / 24, c = i % 24;
            int n = row0 + r;
            if (n < NN) {
                float4 v = *(float4*)&sC[r * 100 + c * 4];
                atomicAdd((float4*)&g_g[(size_t)batch[n] * DIM] + c, v);
            }
        }
    }
}

// ---------------------------------------------------------------------------
// Pool init + final MLP
// ---------------------------------------------------------------------------
__global__ void zero_g_kernel() {
    int i = blockIdx.x * blockDim.x + threadIdx.x;
    if (i < NG * DIM) g_g[i] = 0.0f;
}
__global__ __launch_bounds__(256) void final_kernel(
    const float* __restrict__ fW1, const float* __restrict__ fb1,
    const float* __restrict__ fW2, const float* __restrict__ fb2,
    float* __restrict__ out)
{
    __shared__ float gs[NG * DIM];
    __shared__ float t1[NG * DIM];
    int tid = threadIdx.x;
    for (int i = tid; i < NG * DIM; i += 256) gs[i] = g_g[i];
    __syncthreads();
    for (int o = tid; o < NG * DIM; o += 256) {
        int gi = o / DIM, j = o % DIM;
        float acc = fb1[j];
#pragma unroll 8
        for (int k = 0; k < DIM; k++)
            acc = fmaf(gs[gi * DIM + k], fW1[k * DIM + j], acc);
        t1[o] = fmaxf(acc, 0.0f);
    }
    __syncthreads();
    if (tid < NG) {
        float acc = fb2[0];
#pragma unroll 8
        for (int k = 0; k < DIM; k++)
            acc = fmaf(t1[tid * DIM + k], fW2[k], acc);
        out[tid] = acc;
    }
}

// ---------------------------------------------------------------------------
extern "C" void kernel_launch(void* const* d_in, const int* in_sizes, int n_in,
                              void* d_out, int out_size) {
    const float* x     = (const float*)d_in[0];
    const int*   ei    = (const int*)d_in[1];
    const int*   batch = (const int*)d_in[2];
    const float* W1    = (const float*)d_in[3];
    const float* b1    = (const float*)d_in[4];
    const float* W2    = (const float*)d_in[5];
    const float* b2    = (const float*)d_in[6];
    const float* eps   = (const float*)d_in[7];
    const float* fW1   = (const float*)d_in[8];
    const float* fb1   = (const float*)d_in[9];
    const float* fW2   = (const float*)d_in[10];
    const float* fb2   = (const float*)d_in[11];
    float*       out   = (float*)d_out;

    static bool attr_done = false;
    if (!attr_done) {
        cudaFuncSetAttribute(layer_fused, cudaFuncAttributeMaxDynamicSharedMemorySize, L_SMEM);
        attr_done = true;
    }

    float *zp, *h0p, *h1p;
    __nv_bfloat16 *w1hp, *w1lp, *w2hp, *w2lp;
    cudaGetSymbolAddress((void**)&zp,   g_z);
    cudaGetSymbolAddress((void**)&h0p,  g_h0);
    cudaGetSymbolAddress((void**)&h1p,  g_h1);
    cudaGetSymbolAddress((void**)&w1hp, g_w1h);
    cudaGetSymbolAddress((void**)&w1lp, g_w1l);
    cudaGetSymbolAddress((void**)&w2hp, g_w2h);
    cudaGetSymbolAddress((void**)&w2lp, g_w2l);
    float* hbufs[2] = {h0p, h1p};

    // CSR build + pool init + weight prep (front of graph)
    zero_deg_kernel<<<(NN + 255) / 256, 256>>>();
    hist_kernel<<<(NE + 255) / 256, 256>>>(ei);
    scan_kernel<<<1, 1024>>>();
    reorder_kernel<<<(NE + 255) / 256, 256>>>(ei);
    zero_g_kernel<<<(NG * DIM + 255) / 256, 256>>>();
    prep_w1<<<216, 256>>>(W1);
    prep_w2<<<216, 256>>>(W2);

    const int tiles = NNP / 128;   // 391
    const float* hin = x;
    for (int l = 0; l < 3; l++) {
        gather_kernel<<<(NN + 7) / 8, 256>>>(hin, eps, l);
        float* hout = hbufs[l & 1];
        int do_pool = (l == 2);
        layer_fused<<<tiles, 512, L_SMEM>>>(
            zp, w1hp + l * 192 * P1, w1lp + l * 192 * P1, b1 + (size_t)l * H2,
            w2hp + l * 96 * P2, w2lp + l * 96 * P2, b2 + (size_t)l * DIM,
            hout, batch, do_pool);
        hin = hout;
    }

    final_kernel<<<1, 256>>>(fW1, fb1, fW2, fb2, out);
}

// round 11
// speedup vs baseline: 1.5124x; 1.2848x over previous
#include <cuda_runtime.h>
#include <cuda_bf16.h>
#include <cstdint>

#define NN 50000
#define NNP 50048          // padded to 391*128
#define NE 800000
#define DIM 96
#define H2 192
#define NG 64
#define P1 104             // GEMM1 smem K stride (elements)
#define P2 200             // GEMM2 smem K stride (elements)
#define CAP 96             // fixed CSR slot capacity per node (mean deg 16, >20 sigma margin)

// ---------------------------------------------------------------------------
// Scratch (static device globals)
// ---------------------------------------------------------------------------
__device__ __nv_bfloat16 g_zh[NNP * DIM];   // z hi (pad rows stay 0)
__device__ __nv_bfloat16 g_zl[NNP * DIM];   // z lo
__device__ float g_h0[NNP * DIM];
__device__ float g_h1[NNP * DIM];
__device__ float g_g [NG * DIM];
__device__ __nv_bfloat16 g_w1h[3 * 192 * P1];
__device__ __nv_bfloat16 g_w1l[3 * 192 * P1];
__device__ __nv_bfloat16 g_w2h[3 * 96 * P2];
__device__ __nv_bfloat16 g_w2l[3 * 96 * P2];
// Slot-CSR
__device__ int g_cnt [NN];
__device__ int g_slot[NN * CAP];

// ---------------------------------------------------------------------------
__device__ __forceinline__ uint32_t pack2(__nv_bfloat16 a, __nv_bfloat16 b) {
    return (uint32_t)__bfloat16_as_ushort(a) | ((uint32_t)__bfloat16_as_ushort(b) << 16);
}
__device__ __forceinline__ void split_bf16(float v, __nv_bfloat16& h, __nv_bfloat16& l) {
    h = __float2bfloat16(v);
    l = __float2bfloat16(v - __bfloat162float(h));
}
__device__ __forceinline__ void mma16816(float* d, const uint32_t* a, const uint32_t* b) {
    asm volatile("mma.sync.aligned.m16n8k16.row.col.f32.bf16.bf16.f32 "
        "{%0,%1,%2,%3}, {%4,%5,%6,%7}, {%8,%9}, {%0,%1,%2,%3};"
        : "+f"(d[0]), "+f"(d[1]), "+f"(d[2]), "+f"(d[3])
        : "r"(a[0]), "r"(a[1]), "r"(a[2]), "r"(a[3]), "r"(b[0]), "r"(b[1]));
}
__device__ __forceinline__ void cp_async16(uint32_t saddr, const void* gptr) {
    asm volatile("cp.async.cg.shared.global [%0], [%1], 16;" :: "r"(saddr), "l"(gptr));
}
#define CP_COMMIT() asm volatile("cp.async.commit_group;" ::: "memory")
#define CP_WAIT(n)  asm volatile("cp.async.wait_group %0;" :: "n"(n) : "memory")

// ---------------------------------------------------------------------------
// Slot-CSR build: zero counts -> scatter edges into fixed slots
// ---------------------------------------------------------------------------
__global__ void zero_cnt_kernel() {
    int i = blockIdx.x * blockDim.x + threadIdx.x;
    if (i < NN) g_cnt[i] = 0;
}
__global__ void fill_slots_kernel(const int* __restrict__ ei) {
    int e = blockIdx.x * blockDim.x + threadIdx.x;
    if (e < NE) {
        int dst = ei[NE + e];
        int pos = atomicAdd(&g_cnt[dst], 1);
        if (pos < CAP) g_slot[dst * CAP + pos] = ei[e];
    }
}

// ---------------------------------------------------------------------------
// Gather: z[n] = (1+eps)*h[n] + sum_{slots[n]} h[src], written as bf16 hi/lo
// ---------------------------------------------------------------------------
__global__ __launch_bounds__(256) void gather_kernel(const float* __restrict__ h,
                                                     const float* __restrict__ eps, int l) {
    int wid = threadIdx.x >> 5, lane = threadIdx.x & 31;
    int n = blockIdx.x * 8 + wid;
    if (n >= NN) return;
    int beg = n * CAP, end = beg + g_cnt[n];
    float a0 = 0.f, a1 = 0.f, a2 = 0.f;
    float b0 = 0.f, b1 = 0.f, b2 = 0.f;
    float c0 = 0.f, c1 = 0.f, c2 = 0.f;
    float e0 = 0.f, e1 = 0.f, e2 = 0.f;
    int e = beg;
    for (; e + 4 <= end; e += 4) {
        int s0 = g_slot[e], s1 = g_slot[e + 1], s2 = g_slot[e + 2], s3 = g_slot[e + 3];
        const float* p0 = h + (size_t)s0 * DIM + lane;
        const float* p1 = h + (size_t)s1 * DIM + lane;
        const float* p2 = h + (size_t)s2 * DIM + lane;
        const float* p3 = h + (size_t)s3 * DIM + lane;
        a0 += p0[0];  a1 += p0[32];  a2 += p0[64];
        b0 += p1[0];  b1 += p1[32];  b2 += p1[64];
        c0 += p2[0];  c1 += p2[32];  c2 += p2[64];
        e0 += p3[0];  e1 += p3[32];  e2 += p3[64];
    }
    for (; e < end; e++) {
        const float* p = h + (size_t)g_slot[e] * DIM + lane;
        a0 += p[0]; a1 += p[32]; a2 += p[64];
    }
    float sc = 1.0f + eps[l];
    const float* hp = h + (size_t)n * DIM + lane;
    float z0 = fmaf(sc, hp[0],  (a0 + b0) + (c0 + e0));
    float z1 = fmaf(sc, hp[32], (a1 + b1) + (c1 + e1));
    float z2 = fmaf(sc, hp[64], (a2 + b2) + (c2 + e2));
    __nv_bfloat16 h0, l0, h1, l1, h2, l2;
    split_bf16(z0, h0, l0); split_bf16(z1, h1, l1); split_bf16(z2, h2, l2);
    size_t o = (size_t)n * DIM + lane;
    g_zh[o]      = h0;  g_zl[o]      = l0;
    g_zh[o + 32] = h1;  g_zl[o + 32] = l1;
    g_zh[o + 64] = h2;  g_zl[o + 64] = l2;
}

// ---------------------------------------------------------------------------
// Weight prep
// ---------------------------------------------------------------------------
__global__ void prep_w1(const float* __restrict__ W1) {
    int i = blockIdx.x * blockDim.x + threadIdx.x;
    if (i >= 3 * 192 * 96) return;
    int l = i / 18432, r = i % 18432;
    int n = r / 96, k = r % 96;
    float v = W1[(size_t)l * 96 * 192 + k * 192 + n];
    __nv_bfloat16 h, lo; split_bf16(v, h, lo);
    g_w1h[l * 192 * P1 + n * P1 + k] = h;
    g_w1l[l * 192 * P1 + n * P1 + k] = lo;
}
__global__ void prep_w2(const float* __restrict__ W2) {
    int i = blockIdx.x * blockDim.x + threadIdx.x;
    if (i >= 3 * 96 * 192) return;
    int l = i / 18432, r = i % 18432;
    int n = r / 192, k = r % 192;
    float v = W2[(size_t)l * 192 * 96 + k * 96 + n];
    __nv_bfloat16 h, lo; split_bf16(v, h, lo);
    g_w2h[l * 96 * P2 + n * P2 + k] = h;
    g_w2l[l * 96 * P2 + n * P2 + k] = lo;
}

// ---------------------------------------------------------------------------
// Fused layer (512 threads, 16 warps 4x4): h' = relu(relu(z@W1+b1)@W2+b2)
// cp.async: group0 = B1+biases+A (gemm1 gate), group1 = B2 (gemm2 gate).
// A arrives pre-split as bf16 hi/lo from the gather.
// ---------------------------------------------------------------------------
#define OFF_B1S  0
#define OFF_B2S  768
#define OFF_AH   1280
#define OFF_AL   27904
#define OFF_B1H  54528
#define OFF_B1L  94464
#define OFF_B2H  134400
#define OFF_B2L  172800
#define OFF_Z1H  1280
#define OFF_Z1L  52480
#define OFF_SC   1280
#define L_SMEM   211200

__global__ __launch_bounds__(512) void layer_fused(
    const __nv_bfloat16* __restrict__ Azh, const __nv_bfloat16* __restrict__ Azl,
    const __nv_bfloat16* __restrict__ B1h, const __nv_bfloat16* __restrict__ B1l,
    const float* __restrict__ bias1,
    const __nv_bfloat16* __restrict__ B2h, const __nv_bfloat16* __restrict__ B2l,
    const float* __restrict__ bias2, float* __restrict__ C,
    const int* __restrict__ batch, int do_pool)
{
    extern __shared__ char sm[];
    float* b1s = (float*)(sm + OFF_B1S);
    float* b2s = (float*)(sm + OFF_B2S);
    __nv_bfloat16* sAh  = (__nv_bfloat16*)(sm + OFF_AH);
    __nv_bfloat16* sAl  = (__nv_bfloat16*)(sm + OFF_AL);
    __nv_bfloat16* sB1h = (__nv_bfloat16*)(sm + OFF_B1H);
    __nv_bfloat16* sB1l = (__nv_bfloat16*)(sm + OFF_B1L);
    __nv_bfloat16* sB2h = (__nv_bfloat16*)(sm + OFF_B2H);
    __nv_bfloat16* sB2l = (__nv_bfloat16*)(sm + OFF_B2L);
    __nv_bfloat16* z1h  = (__nv_bfloat16*)(sm + OFF_Z1H);
    __nv_bfloat16* z1l  = (__nv_bfloat16*)(sm + OFF_Z1L);
    int tid = threadIdx.x, lane = tid & 31, wid = tid >> 5;
    int row0 = blockIdx.x * 128;
    uint32_t smb = (uint32_t)__cvta_generic_to_shared(sm);

    // group0: B1 + biases + A tile (gemm1 gate)
    for (int i = tid; i < 2496; i += 512) {
        cp_async16(smb + OFF_B1H + i * 16, (const char*)B1h + i * 16);
        cp_async16(smb + OFF_B1L + i * 16, (const char*)B1l + i * 16);
    }
    // A: 128 rows x 96 bf16 = 12 x 16B chunks per row, strided dest (208 B/row)
    for (int i = tid; i < 1536; i += 512) {
        int r = i / 12, c = i % 12;
        uint32_t doff = (uint32_t)r * 208 + c * 16;
        size_t goff = (size_t)(row0 + r) * DIM + c * 8;
        cp_async16(smb + OFF_AH + doff, Azh + goff);
        cp_async16(smb + OFF_AL + doff, Azl + goff);
    }
    if (tid < 48) cp_async16(smb + OFF_B1S + tid * 16, (const char*)bias1 + tid * 16);
    if (tid >= 64 && tid < 88)
        cp_async16(smb + OFF_B2S + (tid - 64) * 16, (const char*)bias2 + (tid - 64) * 16);
    CP_COMMIT();
    // group1: B2 (gemm2 gate)
    for (int i = tid; i < 2400; i += 512) {
        cp_async16(smb + OFF_B2H + i * 16, (const char*)B2h + i * 16);
        cp_async16(smb + OFF_B2L + i * 16, (const char*)B2l + i * 16);
    }
    CP_COMMIT();

    CP_WAIT(1);
    __syncthreads();

    int wm = wid >> 2, wn = wid & 3;         // 4x4 warp grid
    int arow = wm * 32 + (lane >> 2);
    int kc = (lane & 3) * 2;

    // ---- gemm1: 128x192, K=96; warp tile 32x48 ----
    {
        float d[2][6][4];
#pragma unroll
        for (int m = 0; m < 2; m++)
#pragma unroll
            for (int j = 0; j < 6; j++)
#pragma unroll
                for (int t = 0; t < 4; t++) d[m][j][t] = 0.0f;

#pragma unroll
        for (int k0 = 0; k0 < 96; k0 += 16) {
            uint32_t ah[2][4], al[2][4];
#pragma unroll
            for (int m = 0; m < 2; m++) {
                uint32_t o = (uint32_t)(arow + m * 16) * P1 + k0 + kc;
                ah[m][0] = *(uint32_t*)&sAh[o];
                ah[m][1] = *(uint32_t*)&sAh[o + 8 * P1];
                ah[m][2] = *(uint32_t*)&sAh[o + 8];
                ah[m][3] = *(uint32_t*)&sAh[o + 8 * P1 + 8];
                al[m][0] = *(uint32_t*)&sAl[o];
                al[m][1] = *(uint32_t*)&sAl[o + 8 * P1];
                al[m][2] = *(uint32_t*)&sAl[o + 8];
                al[m][3] = *(uint32_t*)&sAl[o + 8 * P1 + 8];
            }
#pragma unroll
            for (int j = 0; j < 6; j++) {
                uint32_t ob = (uint32_t)(wn * 48 + j * 8 + (lane >> 2)) * P1 + k0 + kc;
                uint32_t bh[2] = { *(uint32_t*)&sB1h[ob], *(uint32_t*)&sB1h[ob + 8] };
                uint32_t bl[2] = { *(uint32_t*)&sB1l[ob], *(uint32_t*)&sB1l[ob + 8] };
#pragma unroll
                for (int m = 0; m < 2; m++) {
                    mma16816(d[m][j], ah[m], bh);
                    mma16816(d[m][j], ah[m], bl);
                    mma16816(d[m][j], al[m], bh);
                }
            }
        }
        __syncthreads();

#pragma unroll
        for (int m = 0; m < 2; m++) {
            int r1 = wm * 32 + m * 16 + (lane >> 2);
#pragma unroll
            for (int j = 0; j < 6; j++) {
                int c0 = wn * 48 + j * 8 + (lane & 3) * 2;
                float v0 = fmaxf(d[m][j][0] + b1s[c0],     0.0f);
                float v1 = fmaxf(d[m][j][1] + b1s[c0 + 1], 0.0f);
                float v2 = fmaxf(d[m][j][2] + b1s[c0],     0.0f);
                float v3 = fmaxf(d[m][j][3] + b1s[c0 + 1], 0.0f);
                __nv_bfloat16 h0,l0,h1,l1,h2,l2,h3,l3;
                split_bf16(v0,h0,l0); split_bf16(v1,h1,l1);
                split_bf16(v2,h2,l2); split_bf16(v3,h3,l3);
                *(uint32_t*)&z1h[r1 * P2 + c0]       = pack2(h0, h1);
                *(uint32_t*)&z1l[r1 * P2 + c0]       = pack2(l0, l1);
                *(uint32_t*)&z1h[(r1 + 8) * P2 + c0] = pack2(h2, h3);
                *(uint32_t*)&z1l[(r1 + 8) * P2 + c0] = pack2(l2, l3);
            }
        }
    }
    CP_WAIT(0);
    __syncthreads();

    // ---- gemm2: 128x96, K=192; warp tile 32x24 ----
    float d2[2][3][4];
#pragma unroll
    for (int m = 0; m < 2; m++)
#pragma unroll
        for (int j = 0; j < 3; j++)
#pragma unroll
            for (int t = 0; t < 4; t++) d2[m][j][t] = 0.0f;

#pragma unroll
    for (int k0 = 0; k0 < 192; k0 += 16) {
        uint32_t ah[2][4], al[2][4];
#pragma unroll
        for (int m = 0; m < 2; m++) {
            uint32_t o = (uint32_t)(arow + m * 16) * P2 + k0 + kc;
            ah[m][0] = *(uint32_t*)&z1h[o];
            ah[m][1] = *(uint32_t*)&z1h[o + 8 * P2];
            ah[m][2] = *(uint32_t*)&z1h[o + 8];
            ah[m][3] = *(uint32_t*)&z1h[o + 8 * P2 + 8];
            al[m][0] = *(uint32_t*)&z1l[o];
            al[m][1] = *(uint32_t*)&z1l[o + 8 * P2];
            al[m][2] = *(uint32_t*)&z1l[o + 8];
            al[m][3] = *(uint32_t*)&z1l[o + 8 * P2 + 8];
        }
#pragma unroll
        for (int j = 0; j < 3; j++) {
            uint32_t ob = (uint32_t)(wn * 24 + j * 8 + (lane >> 2)) * P2 + k0 + kc;
            uint32_t bh[2] = { *(uint32_t*)&sB2h[ob], *(uint32_t*)&sB2h[ob + 8] };
            uint32_t bl[2] = { *(uint32_t*)&sB2l[ob], *(uint32_t*)&sB2l[ob + 8] };
#pragma unroll
            for (int m = 0; m < 2; m++) {
                mma16816(d2[m][j], ah[m], bh);
                mma16816(d2[m][j], ah[m], bl);
                mma16816(d2[m][j], al[m], bh);
            }
        }
    }
    __syncthreads();   // z1 dead; reuse as sC

    float* sC = (float*)(sm + OFF_SC);               // [128][100]
#pragma unroll
    for (int m = 0; m < 2; m++) {
        int r1 = wm * 32 + m * 16 + (lane >> 2);
#pragma unroll
        for (int j = 0; j < 3; j++) {
            int c0 = wn * 24 + j * 8 + (lane & 3) * 2;
            *(float2*)&sC[r1 * 100 + c0] = make_float2(
                fmaxf(d2[m][j][0] + b2s[c0],     0.0f),
                fmaxf(d2[m][j][1] + b2s[c0 + 1], 0.0f));
            *(float2*)&sC[(r1 + 8) * 100 + c0] = make_float2(
                fmaxf(d2[m][j][2] + b2s[c0],     0.0f),
                fmaxf(d2[m][j][3] + b2s[c0 + 1], 0.0f));
        }
    }
    __syncthreads();

    if (!do_pool) {
        float4* gC = (float4*)(C + (size_t)row0 * DIM);
        for (int i = tid; i < 3072; i += 512) {
            int r = i / 24, c = i % 24;
            gC[i] = *(float4*)&sC[r * 100 + c * 4];
        }
    } else {
        // last layer: pool directly into g_g (g_g pre-zeroed)
        for (int i = tid; i < 3072; i += 512) {
            int r = i / 24, c = i % 24;
            int n = row0 + r;
            if (n < NN) {
                float4 v = *(float4*)&sC[r * 100 + c * 4];
                atomicAdd((float4*)&g_g[(size_t)batch[n] * DIM] + c, v);
            }
        }
    }
}

// ---------------------------------------------------------------------------
// Pool init + final MLP
// ---------------------------------------------------------------------------
__global__ void zero_g_kernel() {
    int i = blockIdx.x * blockDim.x + threadIdx.x;
    if (i < NG * DIM) g_g[i] = 0.0f;
}
__global__ __launch_bounds__(256) void final_kernel(
    const float* __restrict__ fW1, const float* __restrict__ fb1,
    const float* __restrict__ fW2, const float* __restrict__ fb2,
    float* __restrict__ out)
{
    __shared__ float gs[NG * DIM];
    __shared__ float t1[NG * DIM];
    int tid = threadIdx.x;
    for (int i = tid; i < NG * DIM; i += 256) gs[i] = g_g[i];
    __syncthreads();
    for (int o = tid; o < NG * DIM; o += 256) {
        int gi = o / DIM, j = o % DIM;
        float acc = fb1[j];
#pragma unroll 8
        for (int k = 0; k < DIM; k++)
            acc = fmaf(gs[gi * DIM + k], fW1[k * DIM + j], acc);
        t1[o] = fmaxf(acc, 0.0f);
    }
    __syncthreads();
    if (tid < NG) {
        float acc = fb2[0];
#pragma unroll 8
        for (int k = 0; k < DIM; k++)
            acc = fmaf(t1[tid * DIM + k], fW2[k], acc);
        out[tid] = acc;
    }
}

// ---------------------------------------------------------------------------
extern "C" void kernel_launch(void* const* d_in, const int* in_sizes, int n_in,
                              void* d_out, int out_size) {
    const float* x     = (const float*)d_in[0];
    const int*   ei    = (const int*)d_in[1];
    const int*   batch = (const int*)d_in[2];
    const float* W1    = (const float*)d_in[3];
    const float* b1    = (const float*)d_in[4];
    const float* W2    = (const float*)d_in[5];
    const float* b2    = (const float*)d_in[6];
    const float* eps   = (const float*)d_in[7];
    const float* fW1   = (const float*)d_in[8];
    const float* fb1   = (const float*)d_in[9];
    const float* fW2   = (const float*)d_in[10];
    const float* fb2   = (const float*)d_in[11];
    float*       out   = (float*)d_out;

    static bool attr_done = false;
    if (!attr_done) {
        cudaFuncSetAttribute(layer_fused, cudaFuncAttributeMaxDynamicSharedMemorySize, L_SMEM);
        attr_done = true;
    }

    float *h0p, *h1p;
    __nv_bfloat16 *zhp, *zlp, *w1hp, *w1lp, *w2hp, *w2lp;
    cudaGetSymbolAddress((void**)&zhp,  g_zh);
    cudaGetSymbolAddress((void**)&zlp,  g_zl);
    cudaGetSymbolAddress((void**)&h0p,  g_h0);
    cudaGetSymbolAddress((void**)&h1p,  g_h1);
    cudaGetSymbolAddress((void**)&w1hp, g_w1h);
    cudaGetSymbolAddress((void**)&w1lp, g_w1l);
    cudaGetSymbolAddress((void**)&w2hp, g_w2h);
    cudaGetSymbolAddress((void**)&w2lp, g_w2l);
    float* hbufs[2] = {h0p, h1p};

    // Slot-CSR build + pool init + weight prep
    zero_cnt_kernel<<<(NN + 255) / 256, 256>>>();
    fill_slots_kernel<<<(NE + 255) / 256, 256>>>(ei);
    zero_g_kernel<<<(NG * DIM + 255) / 256, 256>>>();
    prep_w1<<<216, 256>>>(W1);
    prep_w2<<<216, 256>>>(W2);

    const int tiles = NNP / 128;   // 391
    const float* hin = x;
    for (int l = 0; l < 3; l++) {
        gather_kernel<<<(NN + 7) / 8, 256>>>(hin, eps, l);
        float* hout = hbufs[l & 1];
        int do_pool = (l == 2);
        layer_fused<<<tiles, 512, L_SMEM>>>(
            zhp, zlp,
            w1hp + l * 192 * P1, w1lp + l * 192 * P1, b1 + (size_t)l * H2,
            w2hp + l * 96 * P2, w2lp + l * 96 * P2, b2 + (size_t)l * DIM,
            hout, batch, do_pool);
        hin = hout;
    }

    final_kernel<<<1, 256>>>(fW1, fb1, fW2, fb2, out);
}

// round 12
// speedup vs baseline: 1.5413x; 1.0191x over previous
#include <cuda_runtime.h>
#include <cuda_bf16.h>
#include <cstdint>

#define NN 50000
#define NNP 50048          // padded to 391*128
#define NE 800000
#define DIM 96
#define H2 192
#define NG 64
#define P1 104             // GEMM1 smem K stride (elements)
#define P2 200             // GEMM2 smem K stride (elements)
#define CAP 96             // fixed CSR slot capacity per node (mean deg 16, >20 sigma margin)

// ---------------------------------------------------------------------------
// Scratch (static device globals)
// ---------------------------------------------------------------------------
__device__ __nv_bfloat16 g_zh[NNP * DIM];   // z hi (pad rows stay 0)
__device__ __nv_bfloat16 g_zl[NNP * DIM];   // z lo
__device__ float g_h0[NNP * DIM];
__device__ float g_h1[NNP * DIM];
__device__ float g_g [NG * DIM];
__device__ __nv_bfloat16 g_w1h[3 * 192 * P1];
__device__ __nv_bfloat16 g_w1l[3 * 192 * P1];
__device__ __nv_bfloat16 g_w2h[3 * 96 * P2];
__device__ __nv_bfloat16 g_w2l[3 * 96 * P2];
// Slot-CSR
__device__ int g_cnt [NN];
__device__ int g_slot[NN * CAP];

// ---------------------------------------------------------------------------
__device__ __forceinline__ uint32_t pack2(__nv_bfloat16 a, __nv_bfloat16 b) {
    return (uint32_t)__bfloat16_as_ushort(a) | ((uint32_t)__bfloat16_as_ushort(b) << 16);
}
__device__ __forceinline__ void split_bf16(float v, __nv_bfloat16& h, __nv_bfloat16& l) {
    h = __float2bfloat16(v);
    l = __float2bfloat16(v - __bfloat162float(h));
}
__device__ __forceinline__ void mma16816(float* d, const uint32_t* a, const uint32_t* b) {
    asm volatile("mma.sync.aligned.m16n8k16.row.col.f32.bf16.bf16.f32 "
        "{%0,%1,%2,%3}, {%4,%5,%6,%7}, {%8,%9}, {%0,%1,%2,%3};"
        : "+f"(d[0]), "+f"(d[1]), "+f"(d[2]), "+f"(d[3])
        : "r"(a[0]), "r"(a[1]), "r"(a[2]), "r"(a[3]), "r"(b[0]), "r"(b[1]));
}
__device__ __forceinline__ void cp_async16(uint32_t saddr, const void* gptr) {
    asm volatile("cp.async.cg.shared.global [%0], [%1], 16;" :: "r"(saddr), "l"(gptr));
}
#define CP_COMMIT() asm volatile("cp.async.commit_group;" ::: "memory")
#define CP_WAIT(n)  asm volatile("cp.async.wait_group %0;" :: "n"(n) : "memory")

// ---------------------------------------------------------------------------
// Slot-CSR build: zero counts -> scatter edges into fixed slots
// ---------------------------------------------------------------------------
__global__ void zero_cnt_kernel() {
    int i = blockIdx.x * blockDim.x + threadIdx.x;
    if (i < NN) g_cnt[i] = 0;
}
__global__ void fill_slots_kernel(const int* __restrict__ ei) {
    int e = blockIdx.x * blockDim.x + threadIdx.x;
    if (e < NE) {
        int dst = ei[NE + e];
        int pos = atomicAdd(&g_cnt[dst], 1);
        if (pos < CAP) g_slot[dst * CAP + pos] = ei[e];
    }
}

// ---------------------------------------------------------------------------
// Gather (float4): z[n] = (1+eps)*h[n] + sum_{slots[n]} h[src]
// One warp per node; lanes 0..23 own 4 consecutive cols -> 1 LDG.128/edge-row.
// Output written pre-split as bf16 hi/lo (uint2 per lane per buffer).
// ---------------------------------------------------------------------------
__global__ __launch_bounds__(256) void gather_kernel(const float* __restrict__ h,
                                                     const float* __restrict__ eps, int l) {
    int wid = threadIdx.x >> 5, lane = threadIdx.x & 31;
    int n = blockIdx.x * 8 + wid;
    if (n >= NN || lane >= 24) return;
    int c4 = lane * 4;
    int beg = n * CAP, end = beg + g_cnt[n];
    float4 A = make_float4(0.f, 0.f, 0.f, 0.f);
    float4 B = A, Cv = A, D = A;
    int e = beg;
    for (; e + 4 <= end; e += 4) {
        int s0 = g_slot[e], s1 = g_slot[e + 1], s2 = g_slot[e + 2], s3 = g_slot[e + 3];
        float4 v0 = *(const float4*)(h + (size_t)s0 * DIM + c4);
        float4 v1 = *(const float4*)(h + (size_t)s1 * DIM + c4);
        float4 v2 = *(const float4*)(h + (size_t)s2 * DIM + c4);
        float4 v3 = *(const float4*)(h + (size_t)s3 * DIM + c4);
        A.x += v0.x; A.y += v0.y; A.z += v0.z; A.w += v0.w;
        B.x += v1.x; B.y += v1.y; B.z += v1.z; B.w += v1.w;
        Cv.x += v2.x; Cv.y += v2.y; Cv.z += v2.z; Cv.w += v2.w;
        D.x += v3.x; D.y += v3.y; D.z += v3.z; D.w += v3.w;
    }
    for (; e < end; e++) {
        float4 v = *(const float4*)(h + (size_t)g_slot[e] * DIM + c4);
        A.x += v.x; A.y += v.y; A.z += v.z; A.w += v.w;
    }
    float sc = 1.0f + eps[l];
    float4 own = *(const float4*)(h + (size_t)n * DIM + c4);
    float z0 = fmaf(sc, own.x, (A.x + B.x) + (Cv.x + D.x));
    float z1 = fmaf(sc, own.y, (A.y + B.y) + (Cv.y + D.y));
    float z2 = fmaf(sc, own.z, (A.z + B.z) + (Cv.z + D.z));
    float z3 = fmaf(sc, own.w, (A.w + B.w) + (Cv.w + D.w));
    __nv_bfloat16 h0,l0,h1,l1,h2,l2,h3,l3;
    split_bf16(z0, h0, l0); split_bf16(z1, h1, l1);
    split_bf16(z2, h2, l2); split_bf16(z3, h3, l3);
    size_t o = (size_t)n * DIM + c4;
    *(uint2*)&g_zh[o] = make_uint2(pack2(h0, h1), pack2(h2, h3));
    *(uint2*)&g_zl[o] = make_uint2(pack2(l0, l1), pack2(l2, l3));
}

// ---------------------------------------------------------------------------
// Weight prep
// ---------------------------------------------------------------------------
__global__ void prep_w1(const float* __restrict__ W1) {
    int i = blockIdx.x * blockDim.x + threadIdx.x;
    if (i >= 3 * 192 * 96) return;
    int l = i / 18432, r = i % 18432;
    int n = r / 96, k = r % 96;
    float v = W1[(size_t)l * 96 * 192 + k * 192 + n];
    __nv_bfloat16 h, lo; split_bf16(v, h, lo);
    g_w1h[l * 192 * P1 + n * P1 + k] = h;
    g_w1l[l * 192 * P1 + n * P1 + k] = lo;
}
__global__ void prep_w2(const float* __restrict__ W2) {
    int i = blockIdx.x * blockDim.x + threadIdx.x;
    if (i >= 3 * 96 * 192) return;
    int l = i / 18432, r = i % 18432;
    int n = r / 192, k = r % 192;
    float v = W2[(size_t)l * 192 * 96 + k * 96 + n];
    __nv_bfloat16 h, lo; split_bf16(v, h, lo);
    g_w2h[l * 96 * P2 + n * P2 + k] = h;
    g_w2l[l * 96 * P2 + n * P2 + k] = lo;
}

// ---------------------------------------------------------------------------
// Fused layer (512 threads, 16 warps 4x4): h' = relu(relu(z@W1+b1)@W2+b2)
// cp.async: group0 = B1+biases+A (gemm1 gate), group1 = B2 (gemm2 gate).
// A arrives pre-split as bf16 hi/lo from the gather.
// ---------------------------------------------------------------------------
#define OFF_B1S  0
#define OFF_B2S  768
#define OFF_AH   1280
#define OFF_AL   27904
#define OFF_B1H  54528
#define OFF_B1L  94464
#define OFF_B2H  134400
#define OFF_B2L  172800
#define OFF_Z1H  1280
#define OFF_Z1L  52480
#define OFF_SC   1280
#define L_SMEM   211200

__global__ __launch_bounds__(512) void layer_fused(
    const __nv_bfloat16* __restrict__ Azh, const __nv_bfloat16* __restrict__ Azl,
    const __nv_bfloat16* __restrict__ B1h, const __nv_bfloat16* __restrict__ B1l,
    const float* __restrict__ bias1,
    const __nv_bfloat16* __restrict__ B2h, const __nv_bfloat16* __restrict__ B2l,
    const float* __restrict__ bias2, float* __restrict__ C,
    const int* __restrict__ batch, int do_pool)
{
    extern __shared__ char sm[];
    float* b1s = (float*)(sm + OFF_B1S);
    float* b2s = (float*)(sm + OFF_B2S);
    __nv_bfloat16* sAh  = (__nv_bfloat16*)(sm + OFF_AH);
    __nv_bfloat16* sAl  = (__nv_bfloat16*)(sm + OFF_AL);
    __nv_bfloat16* sB1h = (__nv_bfloat16*)(sm + OFF_B1H);
    __nv_bfloat16* sB1l = (__nv_bfloat16*)(sm + OFF_B1L);
    __nv_bfloat16* sB2h = (__nv_bfloat16*)(sm + OFF_B2H);
    __nv_bfloat16* sB2l = (__nv_bfloat16*)(sm + OFF_B2L);
    __nv_bfloat16* z1h  = (__nv_bfloat16*)(sm + OFF_Z1H);
    __nv_bfloat16* z1l  = (__nv_bfloat16*)(sm + OFF_Z1L);
    int tid = threadIdx.x, lane = tid & 31, wid = tid >> 5;
    int row0 = blockIdx.x * 128;
    uint32_t smb = (uint32_t)__cvta_generic_to_shared(sm);

    // group0: B1 + biases + A tile (gemm1 gate)
    for (int i = tid; i < 2496; i += 512) {
        cp_async16(smb + OFF_B1H + i * 16, (const char*)B1h + i * 16);
        cp_async16(smb + OFF_B1L + i * 16, (const char*)B1l + i * 16);
    }
    // A: 128 rows x 96 bf16 = 12 x 16B chunks per row, strided dest (208 B/row)
    for (int i = tid; i < 1536; i += 512) {
        int r = i / 12, c = i % 12;
        uint32_t doff = (uint32_t)r * 208 + c * 16;
        size_t goff = (size_t)(row0 + r) * DIM + c * 8;
        cp_async16(smb + OFF_AH + doff, Azh + goff);
        cp_async16(smb + OFF_AL + doff, Azl + goff);
    }
    if (tid < 48) cp_async16(smb + OFF_B1S + tid * 16, (const char*)bias1 + tid * 16);
    if (tid >= 64 && tid < 88)
        cp_async16(smb + OFF_B2S + (tid - 64) * 16, (const char*)bias2 + (tid - 64) * 16);
    CP_COMMIT();
    // group1: B2 (gemm2 gate)
    for (int i = tid; i < 2400; i += 512) {
        cp_async16(smb + OFF_B2H + i * 16, (const char*)B2h + i * 16);
        cp_async16(smb + OFF_B2L + i * 16, (const char*)B2l + i * 16);
    }
    CP_COMMIT();

    CP_WAIT(1);
    __syncthreads();

    int wm = wid >> 2, wn = wid & 3;         // 4x4 warp grid
    int arow = wm * 32 + (lane >> 2);
    int kc = (lane & 3) * 2;

    // ---- gemm1: 128x192, K=96; warp tile 32x48 ----
    {
        float d[2][6][4];
#pragma unroll
        for (int m = 0; m < 2; m++)
#pragma unroll
            for (int j = 0; j < 6; j++)
#pragma unroll
                for (int t = 0; t < 4; t++) d[m][j][t] = 0.0f;

#pragma unroll
        for (int k0 = 0; k0 < 96; k0 += 16) {
            uint32_t ah[2][4], al[2][4];
#pragma unroll
            for (int m = 0; m < 2; m++) {
                uint32_t o = (uint32_t)(arow + m * 16) * P1 + k0 + kc;
                ah[m][0] = *(uint32_t*)&sAh[o];
                ah[m][1] = *(uint32_t*)&sAh[o + 8 * P1];
                ah[m][2] = *(uint32_t*)&sAh[o + 8];
                ah[m][3] = *(uint32_t*)&sAh[o + 8 * P1 + 8];
                al[m][0] = *(uint32_t*)&sAl[o];
                al[m][1] = *(uint32_t*)&sAl[o + 8 * P1];
                al[m][2] = *(uint32_t*)&sAl[o + 8];
                al[m][3] = *(uint32_t*)&sAl[o + 8 * P1 + 8];
            }
#pragma unroll
            for (int j = 0; j < 6; j++) {
                uint32_t ob = (uint32_t)(wn * 48 + j * 8 + (lane >> 2)) * P1 + k0 + kc;
                uint32_t bh[2] = { *(uint32_t*)&sB1h[ob], *(uint32_t*)&sB1h[ob + 8] };
                uint32_t bl[2] = { *(uint32_t*)&sB1l[ob], *(uint32_t*)&sB1l[ob + 8] };
#pragma unroll
                for (int m = 0; m < 2; m++) {
                    mma16816(d[m][j], ah[m], bh);
                    mma16816(d[m][j], ah[m], bl);
                    mma16816(d[m][j], al[m], bh);
                }
            }
        }
        __syncthreads();

#pragma unroll
        for (int m = 0; m < 2; m++) {
            int r1 = wm * 32 + m * 16 + (lane >> 2);
#pragma unroll
            for (int j = 0; j < 6; j++) {
                int c0 = wn * 48 + j * 8 + (lane & 3) * 2;
                float v0 = fmaxf(d[m][j][0] + b1s[c0],     0.0f);
                float v1 = fmaxf(d[m][j][1] + b1s[c0 + 1], 0.0f);
                float v2 = fmaxf(d[m][j][2] + b1s[c0],     0.0f);
                float v3 = fmaxf(d[m][j][3] + b1s[c0 + 1], 0.0f);
                __nv_bfloat16 h0,l0,h1,l1,h2,l2,h3,l3;
                split_bf16(v0,h0,l0); split_bf16(v1,h1,l1);
                split_bf16(v2,h2,l2); split_bf16(v3,h3,l3);
                *(uint32_t*)&z1h[r1 * P2 + c0]       = pack2(h0, h1);
                *(uint32_t*)&z1l[r1 * P2 + c0]       = pack2(l0, l1);
                *(uint32_t*)&z1h[(r1 + 8) * P2 + c0] = pack2(h2, h3);
                *(uint32_t*)&z1l[(r1 + 8) * P2 + c0] = pack2(l2, l3);
            }
        }
    }
    CP_WAIT(0);
    __syncthreads();

    // ---- gemm2: 128x96, K=192; warp tile 32x24 ----
    float d2[2][3][4];
#pragma unroll
    for (int m = 0; m < 2; m++)
#pragma unroll
        for (int j = 0; j < 3; j++)
#pragma unroll
            for (int t = 0; t < 4; t++) d2[m][j][t] = 0.0f;

#pragma unroll
    for (int k0 = 0; k0 < 192; k0 += 16) {
        uint32_t ah[2][4], al[2][4];
#pragma unroll
        for (int m = 0; m < 2; m++) {
            uint32_t o = (uint32_t)(arow + m * 16) * P2 + k0 + kc;
            ah[m][0] = *(uint32_t*)&z1h[o];
            ah[m][1] = *(uint32_t*)&z1h[o + 8 * P2];
            ah[m][2] = *(uint32_t*)&z1h[o + 8];
            ah[m][3] = *(uint32_t*)&z1h[o + 8 * P2 + 8];
            al[m][0] = *(uint32_t*)&z1l[o];
            al[m][1] = *(uint32_t*)&z1l[o + 8 * P2];
            al[m][2] = *(uint32_t*)&z1l[o + 8];
            al[m][3] = *(uint32_t*)&z1l[o + 8 * P2 + 8];
        }
#pragma unroll
        for (int j = 0; j < 3; j++) {
            uint32_t ob = (uint32_t)(wn * 24 + j * 8 + (lane >> 2)) * P2 + k0 + kc;
            uint32_t bh[2] = { *(uint32_t*)&sB2h[ob], *(uint32_t*)&sB2h[ob + 8] };
            uint32_t bl[2] = { *(uint32_t*)&sB2l[ob], *(uint32_t*)&sB2l[ob + 8] };
#pragma unroll
            for (int m = 0; m < 2; m++) {
                mma16816(d2[m][j], ah[m], bh);
                mma16816(d2[m][j], ah[m], bl);
                mma16816(d2[m][j], al[m], bh);
            }
        }
    }
    __syncthreads();   // z1 dead; reuse as sC

    float* sC = (float*)(sm + OFF_SC);               // [128][100]
#pragma unroll
    for (int m = 0; m < 2; m++) {
        int r1 = wm * 32 + m * 16 + (lane >> 2);
#pragma unroll
        for (int j = 0; j < 3; j++) {
            int c0 = wn * 24 + j * 8 + (lane & 3) * 2;
            *(float2*)&sC[r1 * 100 + c0] = make_float2(
                fmaxf(d2[m][j][0] + b2s[c0],     0.0f),
                fmaxf(d2[m][j][1] + b2s[c0 + 1], 0.0f));
            *(float2*)&sC[(r1 + 8) * 100 + c0] = make_float2(
                fmaxf(d2[m][j][2] + b2s[c0],     0.0f),
                fmaxf(d2[m][j][3] + b2s[c0 + 1], 0.0f));
        }
    }
    __syncthreads();

    if (!do_pool) {
        float4* gC = (float4*)(C + (size_t)row0 * DIM);
        for (int i = tid; i < 3072; i += 512) {
            int r = i / 24, c = i % 24;
            gC[i] = *(float4*)&sC[r * 100 + c * 4];
        }
    } else {
        // last layer: pool directly into g_g (g_g pre-zeroed)
        for (int i = tid; i < 3072; i += 512) {
            int r = i / 24, c = i % 24;
            int n = row0 + r;
            if (n < NN) {
                float4 v = *(float4*)&sC[r * 100 + c * 4];
                atomicAdd((float4*)&g_g[(size_t)batch[n] * DIM] + c, v);
            }
        }
    }
}

// ---------------------------------------------------------------------------
// Pool init + final MLP
// ---------------------------------------------------------------------------
__global__ void zero_g_kernel() {
    int i = blockIdx.x * blockDim.x + threadIdx.x;
    if (i < NG * DIM) g_g[i] = 0.0f;
}
__global__ __launch_bounds__(256) void final_kernel(
    const float* __restrict__ fW1, const float* __restrict__ fb1,
    const float* __restrict__ fW2, const float* __restrict__ fb2,
    float* __restrict__ out)
{
    __shared__ float gs[NG * DIM];
    __shared__ float t1[NG * DIM];
    int tid = threadIdx.x;
    for (int i = tid; i < NG * DIM; i += 256) gs[i] = g_g[i];
    __syncthreads();
    for (int o = tid; o < NG * DIM; o += 256) {
        int gi = o / DIM, j = o % DIM;
        float acc = fb1[j];
#pragma unroll 8
        for (int k = 0; k < DIM; k++)
            acc = fmaf(gs[gi * DIM + k], fW1[k * DIM + j], acc);
        t1[o] = fmaxf(acc, 0.0f);
    }
    __syncthreads();
    if (tid < NG) {
        float acc = fb2[0];
#pragma unroll 8
        for (int k = 0; k < DIM; k++)
            acc = fmaf(t1[tid * DIM + k], fW2[k], acc);
        out[tid] = acc;
    }
}

// ---------------------------------------------------------------------------
extern "C" void kernel_launch(void* const* d_in, const int* in_sizes, int n_in,
                              void* d_out, int out_size) {
    const float* x     = (const float*)d_in[0];
    const int*   ei    = (const int*)d_in[1];
    const int*   batch = (const int*)d_in[2];
    const float* W1    = (const float*)d_in[3];
    const float* b1    = (const float*)d_in[4];
    const float* W2    = (const float*)d_in[5];
    const float* b2    = (const float*)d_in[6];
    const float* eps   = (const float*)d_in[7];
    const float* fW1   = (const float*)d_in[8];
    const float* fb1   = (const float*)d_in[9];
    const float* fW2   = (const float*)d_in[10];
    const float* fb2   = (const float*)d_in[11];
    float*       out   = (float*)d_out;

    static bool attr_done = false;
    if (!attr_done) {
        cudaFuncSetAttribute(layer_fused, cudaFuncAttributeMaxDynamicSharedMemorySize, L_SMEM);
        attr_done = true;
    }

    float *h0p, *h1p;
    __nv_bfloat16 *zhp, *zlp, *w1hp, *w1lp, *w2hp, *w2lp;
    cudaGetSymbolAddress((void**)&zhp,  g_zh);
    cudaGetSymbolAddress((void**)&zlp,  g_zl);
    cudaGetSymbolAddress((void**)&h0p,  g_h0);
    cudaGetSymbolAddress((void**)&h1p,  g_h1);
    cudaGetSymbolAddress((void**)&w1hp, g_w1h);
    cudaGetSymbolAddress((void**)&w1lp, g_w1l);
    cudaGetSymbolAddress((void**)&w2hp, g_w2h);
    cudaGetSymbolAddress((void**)&w2lp, g_w2l);
    float* hbufs[2] = {h0p, h1p};

    // Slot-CSR build + pool init + weight prep
    zero_cnt_kernel<<<(NN + 255) / 256, 256>>>();
    fill_slots_kernel<<<(NE + 255) / 256, 256>>>(ei);
    zero_g_kernel<<<(NG * DIM + 255) / 256, 256>>>();
    prep_w1<<<216, 256>>>(W1);
    prep_w2<<<216, 256>>>(W2);

    const int tiles = NNP / 128;   // 391
    const float* hin = x;
    for (int l = 0; l < 3; l++) {
        gather_kernel<<<(NN + 7) / 8, 256>>>(hin, eps, l);
        float* hout = hbufs[l & 1];
        int do_pool = (l == 2);
        layer_fused<<<tiles, 512, L_SMEM>>>(
            zhp, zlp,
            w1hp + l * 192 * P1, w1lp + l * 192 * P1, b1 + (size_t)l * H2,
            w2hp + l * 96 * P2, w2lp + l * 96 * P2, b2 + (size_t)l * DIM,
            hout, batch, do_pool);
        hin = hout;
    }

    final_kernel<<<1, 256>>>(fW1, fb1, fW2, fb2, out);
}

// round 14
// speedup vs baseline: 1.5644x; 1.0150x over previous
#include <cuda_runtime.h>
#include <cuda_bf16.h>
#include <cstdint>

#define NN 50000
#define NNP 50048          // padded to 391*128
#define NE 800000
#define DIM 96
#define H2 192
#define NG 64
#define P1 104             // GEMM1 smem K stride (elements)
#define P2 200             // GEMM2 smem K stride (elements)
#define CAP 96             // fixed CSR slot capacity per node (mean deg 16, >20 sigma margin)

// ---------------------------------------------------------------------------
// Scratch (static device globals)
// ---------------------------------------------------------------------------
__device__ __nv_bfloat16 g_zh[NNP * DIM];   // z hi (pad rows stay 0)
__device__ __nv_bfloat16 g_zl[NNP * DIM];   // z lo
__device__ float g_h0[NNP * DIM];
__device__ float g_h1[NNP * DIM];
__device__ float g_g [NG * DIM];
__device__ __nv_bfloat16 g_w1h[3 * 192 * P1];
__device__ __nv_bfloat16 g_w1l[3 * 192 * P1];
__device__ __nv_bfloat16 g_w2h[3 * 96 * P2];
__device__ __nv_bfloat16 g_w2l[3 * 96 * P2];
// Slot-CSR
__device__ int g_cnt [NN];
__device__ int g_slot[NN * CAP];

// ---------------------------------------------------------------------------
__device__ __forceinline__ uint32_t pack2(__nv_bfloat16 a, __nv_bfloat16 b) {
    return (uint32_t)__bfloat16_as_ushort(a) | ((uint32_t)__bfloat16_as_ushort(b) << 16);
}
__device__ __forceinline__ void split_bf16(float v, __nv_bfloat16& h, __nv_bfloat16& l) {
    h = __float2bfloat16(v);
    l = __float2bfloat16(v - __bfloat162float(h));
}
__device__ __forceinline__ void mma16816(float* d, const uint32_t* a, const uint32_t* b) {
    asm volatile("mma.sync.aligned.m16n8k16.row.col.f32.bf16.bf16.f32 "
        "{%0,%1,%2,%3}, {%4,%5,%6,%7}, {%8,%9}, {%0,%1,%2,%3};"
        : "+f"(d[0]), "+f"(d[1]), "+f"(d[2]), "+f"(d[3])
        : "r"(a[0]), "r"(a[1]), "r"(a[2]), "r"(a[3]), "r"(b[0]), "r"(b[1]));
}
__device__ __forceinline__ void cp_async16(uint32_t saddr, const void* gptr) {
    asm volatile("cp.async.cg.shared.global [%0], [%1], 16;" :: "r"(saddr), "l"(gptr));
}
#define CP_COMMIT() asm volatile("cp.async.commit_group;" ::: "memory")
#define CP_WAIT(n)  asm volatile("cp.async.wait_group %0;" :: "n"(n) : "memory")

// ---------------------------------------------------------------------------
// Fused init: zero_cnt + zero_g + prep_w1 + prep_w2 in ONE launch.
// Work partition by global index:
//   [0, NN)                      -> g_cnt[i] = 0
//   [NN, NN+6144)                -> g_g[i] = 0
//   [NN+6144, NN+6144+55296)     -> prep W1
//   [NN+61440, NN+61440+55296)   -> prep W2
// ---------------------------------------------------------------------------
#define INIT_TOTAL (NN + NG * DIM + 55296 + 55296)
__global__ void init_kernel(const float* __restrict__ W1, const float* __restrict__ W2) {
    int i = blockIdx.x * blockDim.x + threadIdx.x;
    if (i < NN) {
        g_cnt[i] = 0;
    } else if (i < NN + NG * DIM) {
        g_g[i - NN] = 0.0f;
    } else if (i < NN + NG * DIM + 55296) {
        int j = i - (NN + NG * DIM);
        int l = j / 18432, r = j % 18432;
        int n = r / 96, k = r % 96;
        float v = W1[(size_t)l * 96 * 192 + k * 192 + n];
        __nv_bfloat16 h, lo; split_bf16(v, h, lo);
        g_w1h[l * 192 * P1 + n * P1 + k] = h;
        g_w1l[l * 192 * P1 + n * P1 + k] = lo;
    } else if (i < INIT_TOTAL) {
        int j = i - (NN + NG * DIM + 55296);
        int l = j / 18432, r = j % 18432;
        int n = r / 192, k = r % 192;
        float v = W2[(size_t)l * 192 * 96 + k * 96 + n];
        __nv_bfloat16 h, lo; split_bf16(v, h, lo);
        g_w2h[l * 96 * P2 + n * P2 + k] = h;
        g_w2l[l * 96 * P2 + n * P2 + k] = lo;
    }
}

__global__ void fill_slots_kernel(const int* __restrict__ ei) {
    int e = blockIdx.x * blockDim.x + threadIdx.x;
    if (e < NE) {
        int dst = ei[NE + e];
        int pos = atomicAdd(&g_cnt[dst], 1);
        if (pos < CAP) g_slot[dst * CAP + pos] = ei[e];
    }
}

// ---------------------------------------------------------------------------
// Gather (float4): z[n] = (1+eps)*h[n] + sum_{slots[n]} h[src]
// One warp per node; lanes 0..23 own 4 consecutive cols -> 1 LDG.128/edge-row.
// ---------------------------------------------------------------------------
__global__ __launch_bounds__(256) void gather_kernel(const float* __restrict__ h,
                                                     const float* __restrict__ eps, int l) {
    int wid = threadIdx.x >> 5, lane = threadIdx.x & 31;
    int n = blockIdx.x * 8 + wid;
    if (n >= NN || lane >= 24) return;
    int c4 = lane * 4;
    int beg = n * CAP, end = beg + g_cnt[n];
    float4 A = make_float4(0.f, 0.f, 0.f, 0.f);
    float4 B = A, Cv = A, D = A;
    int e = beg;
    for (; e + 4 <= end; e += 4) {
        int s0 = g_slot[e], s1 = g_slot[e + 1], s2 = g_slot[e + 2], s3 = g_slot[e + 3];
        float4 v0 = *(const float4*)(h + (size_t)s0 * DIM + c4);
        float4 v1 = *(const float4*)(h + (size_t)s1 * DIM + c4);
        float4 v2 = *(const float4*)(h + (size_t)s2 * DIM + c4);
        float4 v3 = *(const float4*)(h + (size_t)s3 * DIM + c4);
        A.x += v0.x; A.y += v0.y; A.z += v0.z; A.w += v0.w;
        B.x += v1.x; B.y += v1.y; B.z += v1.z; B.w += v1.w;
        Cv.x += v2.x; Cv.y += v2.y; Cv.z += v2.z; Cv.w += v2.w;
        D.x += v3.x; D.y += v3.y; D.z += v3.z; D.w += v3.w;
    }
    for (; e < end; e++) {
        float4 v = *(const float4*)(h + (size_t)g_slot[e] * DIM + c4);
        A.x += v.x; A.y += v.y; A.z += v.z; A.w += v.w;
    }
    float sc = 1.0f + eps[l];
    float4 own = *(const float4*)(h + (size_t)n * DIM + c4);
    float z0 = fmaf(sc, own.x, (A.x + B.x) + (Cv.x + D.x));
    float z1 = fmaf(sc, own.y, (A.y + B.y) + (Cv.y + D.y));
    float z2 = fmaf(sc, own.z, (A.z + B.z) + (Cv.z + D.z));
    float z3 = fmaf(sc, own.w, (A.w + B.w) + (Cv.w + D.w));
    __nv_bfloat16 h0,l0,h1,l1,h2,l2,h3,l3;
    split_bf16(z0, h0, l0); split_bf16(z1, h1, l1);
    split_bf16(z2, h2, l2); split_bf16(z3, h3, l3);
    size_t o = (size_t)n * DIM + c4;
    *(uint2*)&g_zh[o] = make_uint2(pack2(h0, h1), pack2(h2, h3));
    *(uint2*)&g_zl[o] = make_uint2(pack2(l0, l1), pack2(l2, l3));
}

// ---------------------------------------------------------------------------
// Fused layer (512 threads, 16 warps 4x4): h' = relu(relu(z@W1+b1)@W2+b2)
// ---------------------------------------------------------------------------
#define OFF_B1S  0
#define OFF_B2S  768
#define OFF_AH   1280
#define OFF_AL   27904
#define OFF_B1H  54528
#define OFF_B1L  94464
#define OFF_B2H  134400
#define OFF_B2L  172800
#define OFF_Z1H  1280
#define OFF_Z1L  52480
#define OFF_SC   1280
#define L_SMEM   211200

__global__ __launch_bounds__(512) void layer_fused(
    const __nv_bfloat16* __restrict__ Azh, const __nv_bfloat16* __restrict__ Azl,
    const __nv_bfloat16* __restrict__ B1h, const __nv_bfloat16* __restrict__ B1l,
    const float* __restrict__ bias1,
    const __nv_bfloat16* __restrict__ B2h, const __nv_bfloat16* __restrict__ B2l,
    const float* __restrict__ bias2, float* __restrict__ C,
    const int* __restrict__ batch, int do_pool)
{
    extern __shared__ char sm[];
    float* b1s = (float*)(sm + OFF_B1S);
    float* b2s = (float*)(sm + OFF_B2S);
    __nv_bfloat16* sAh  = (__nv_bfloat16*)(sm + OFF_AH);
    __nv_bfloat16* sAl  = (__nv_bfloat16*)(sm + OFF_AL);
    __nv_bfloat16* sB1h = (__nv_bfloat16*)(sm + OFF_B1H);
    __nv_bfloat16* sB1l = (__nv_bfloat16*)(sm + OFF_B1L);
    __nv_bfloat16* sB2h = (__nv_bfloat16*)(sm + OFF_B2H);
    __nv_bfloat16* sB2l = (__nv_bfloat16*)(sm + OFF_B2L);
    __nv_bfloat16* z1h  = (__nv_bfloat16*)(sm + OFF_Z1H);
    __nv_bfloat16* z1l  = (__nv_bfloat16*)(sm + OFF_Z1L);
    int tid = threadIdx.x, lane = tid & 31, wid = tid >> 5;
    int row0 = blockIdx.x * 128;
    uint32_t smb = (uint32_t)__cvta_generic_to_shared(sm);

    // group0: B1 + biases + A tile (gemm1 gate)
    for (int i = tid; i < 2496; i += 512) {
        cp_async16(smb + OFF_B1H + i * 16, (const char*)B1h + i * 16);
        cp_async16(smb + OFF_B1L + i * 16, (const char*)B1l + i * 16);
    }
    for (int i = tid; i < 1536; i += 512) {
        int r = i / 12, c = i % 12;
        uint32_t doff = (uint32_t)r * 208 + c * 16;
        size_t goff = (size_t)(row0 + r) * DIM + c * 8;
        cp_async16(smb + OFF_AH + doff, Azh + goff);
        cp_async16(smb + OFF_AL + doff, Azl + goff);
    }
    if (tid < 48) cp_async16(smb + OFF_B1S + tid * 16, (const char*)bias1 + tid * 16);
    if (tid >= 64 && tid < 88)
        cp_async16(smb + OFF_B2S + (tid - 64) * 16, (const char*)bias2 + (tid - 64) * 16);
    CP_COMMIT();
    // group1: B2 (gemm2 gate)
    for (int i = tid; i < 2400; i += 512) {
        cp_async16(smb + OFF_B2H + i * 16, (const char*)B2h + i * 16);
        cp_async16(smb + OFF_B2L + i * 16, (const char*)B2l + i * 16);
    }
    CP_COMMIT();

    CP_WAIT(1);
    __syncthreads();

    int wm = wid >> 2, wn = wid & 3;         // 4x4 warp grid
    int arow = wm * 32 + (lane >> 2);
    int kc = (lane & 3) * 2;

    // ---- gemm1: 128x192, K=96; warp tile 32x48 ----
    {
        float d[2][6][4];
#pragma unroll
        for (int m = 0; m < 2; m++)
#pragma unroll
            for (int j = 0; j < 6; j++)
#pragma unroll
                for (int t = 0; t < 4; t++) d[m][j][t] = 0.0f;

#pragma unroll
        for (int k0 = 0; k0 < 96; k0 += 16) {
            uint32_t ah[2][4], al[2][4];
#pragma unroll
            for (int m = 0; m < 2; m++) {
                uint32_t o = (uint32_t)(arow + m * 16) * P1 + k0 + kc;
                ah[m][0] = *(uint32_t*)&sAh[o];
                ah[m][1] = *(uint32_t*)&sAh[o + 8 * P1];
                ah[m][2] = *(uint32_t*)&sAh[o + 8];
                ah[m][3] = *(uint32_t*)&sAh[o + 8 * P1 + 8];
                al[m][0] = *(uint32_t*)&sAl[o];
                al[m][1] = *(uint32_t*)&sAl[o + 8 * P1];
                al[m][2] = *(uint32_t*)&sAl[o + 8];
                al[m][3] = *(uint32_t*)&sAl[o + 8 * P1 + 8];
            }
#pragma unroll
            for (int j = 0; j < 6; j++) {
                uint32_t ob = (uint32_t)(wn * 48 + j * 8 + (lane >> 2)) * P1 + k0 + kc;
                uint32_t bh[2] = { *(uint32_t*)&sB1h[ob], *(uint32_t*)&sB1h[ob + 8] };
                uint32_t bl[2] = { *(uint32_t*)&sB1l[ob], *(uint32_t*)&sB1l[ob + 8] };
#pragma unroll
                for (int m = 0; m < 2; m++) {
                    mma16816(d[m][j], ah[m], bh);
                    mma16816(d[m][j], ah[m], bl);
                    mma16816(d[m][j], al[m], bh);
                }
            }
        }
        __syncthreads();

#pragma unroll
        for (int m = 0; m < 2; m++) {
            int r1 = wm * 32 + m * 16 + (lane >> 2);
#pragma unroll
            for (int j = 0; j < 6; j++) {
                int c0 = wn * 48 + j * 8 + (lane & 3) * 2;
                float v0 = fmaxf(d[m][j][0] + b1s[c0],     0.0f);
                float v1 = fmaxf(d[m][j][1] + b1s[c0 + 1], 0.0f);
                float v2 = fmaxf(d[m][j][2] + b1s[c0],     0.0f);
                float v3 = fmaxf(d[m][j][3] + b1s[c0 + 1], 0.0f);
                __nv_bfloat16 h0,l0,h1,l1,h2,l2,h3,l3;
                split_bf16(v0,h0,l0); split_bf16(v1,h1,l1);
                split_bf16(v2,h2,l2); split_bf16(v3,h3,l3);
                *(uint32_t*)&z1h[r1 * P2 + c0]       = pack2(h0, h1);
                *(uint32_t*)&z1l[r1 * P2 + c0]       = pack2(l0, l1);
                *(uint32_t*)&z1h[(r1 + 8) * P2 + c0] = pack2(h2, h3);
                *(uint32_t*)&z1l[(r1 + 8) * P2 + c0] = pack2(l2, l3);
            }
        }
    }
    CP_WAIT(0);
    __syncthreads();

    // ---- gemm2: 128x96, K=192; warp tile 32x24 ----
    float d2[2][3][4];
#pragma unroll
    for (int m = 0; m < 2; m++)
#pragma unroll
        for (int j = 0; j < 3; j++)
#pragma unroll
            for (int t = 0; t < 4; t++) d2[m][j][t] = 0.0f;

#pragma unroll
    for (int k0 = 0; k0 < 192; k0 += 16) {
        uint32_t ah[2][4], al[2][4];
#pragma unroll
        for (int m = 0; m < 2; m++) {
            uint32_t o = (uint32_t)(arow + m * 16) * P2 + k0 + kc;
            ah[m][0] = *(uint32_t*)&z1h[o];
            ah[m][1] = *(uint32_t*)&z1h[o + 8 * P2];
            ah[m][2] = *(uint32_t*)&z1h[o + 8];
            ah[m][3] = *(uint32_t*)&z1h[o + 8 * P2 + 8];
            al[m][0] = *(uint32_t*)&z1l[o];
            al[m][1] = *(uint32_t*)&z1l[o + 8 * P2];
            al[m][2] = *(uint32_t*)&z1l[o + 8];
            al[m][3] = *(uint32_t*)&z1l[o + 8 * P2 + 8];
        }
#pragma unroll
        for (int j = 0; j < 3; j++) {
            uint32_t ob = (uint32_t)(wn * 24 + j * 8 + (lane >> 2)) * P2 + k0 + kc;
            uint32_t bh[2] = { *(uint32_t*)&sB2h[ob], *(uint32_t*)&sB2h[ob + 8] };
            uint32_t bl[2] = { *(uint32_t*)&sB2l[ob], *(uint32_t*)&sB2l[ob + 8] };
#pragma unroll
            for (int m = 0; m < 2; m++) {
                mma16816(d2[m][j], ah[m], bh);
                mma16816(d2[m][j], ah[m], bl);
                mma16816(d2[m][j], al[m], bh);
            }
        }
    }
    __syncthreads();   // z1 dead; reuse as sC

    float* sC = (float*)(sm + OFF_SC);               // [128][100]
#pragma unroll
    for (int m = 0; m < 2; m++) {
        int r1 = wm * 32 + m * 16 + (lane >> 2);
#pragma unroll
        for (int j = 0; j < 3; j++) {
            int c0 = wn * 24 + j * 8 + (lane & 3) * 2;
            *(float2*)&sC[r1 * 100 + c0] = make_float2(
                fmaxf(d2[m][j][0] + b2s[c0],     0.0f),
                fmaxf(d2[m][j][1] + b2s[c0 + 1], 0.0f));
            *(float2*)&sC[(r1 + 8) * 100 + c0] = make_float2(
                fmaxf(d2[m][j][2] + b2s[c0],     0.0f),
                fmaxf(d2[m][j][3] + b2s[c0 + 1], 0.0f));
        }
    }
    __syncthreads();

    if (!do_pool) {
        float4* gC = (float4*)(C + (size_t)row0 * DIM);
        for (int i = tid; i < 3072; i += 512) {
            int r = i / 24, c = i % 24;
            gC[i] = *(float4*)&sC[r * 100 + c * 4];
        }
    } else {
        for (int i = tid; i < 3072; i += 512) {
            int r = i / 24, c = i % 24;
            int n = row0 + r;
            if (n < NN) {
                float4 v = *(float4*)&sC[r * 100 + c * 4];
                atomicAdd((float4*)&g_g[(size_t)batch[n] * DIM] + c, v);
            }
        }
    }
}

// ---------------------------------------------------------------------------
// Final MLP
// ---------------------------------------------------------------------------
__global__ __launch_bounds__(256) void final_kernel(
    const float* __restrict__ fW1, const float* __restrict__ fb1,
    const float* __restrict__ fW2, const float* __restrict__ fb2,
    float* __restrict__ out)
{
    __shared__ float gs[NG * DIM];
    __shared__ float t1[NG * DIM];
    int tid = threadIdx.x;
    for (int i = tid; i < NG * DIM; i += 256) gs[i] = g_g[i];
    __syncthreads();
    for (int o = tid; o < NG * DIM; o += 256) {
        int gi = o / DIM, j = o % DIM;
        float acc = fb1[j];
#pragma unroll 8
        for (int k = 0; k < DIM; k++)
            acc = fmaf(gs[gi * DIM + k], fW1[k * DIM + j], acc);
        t1[o] = fmaxf(acc, 0.0f);
    }
    __syncthreads();
    if (tid < NG) {
        float acc = fb2[0];
#pragma unroll 8
        for (int k = 0; k < DIM; k++)
            acc = fmaf(t1[tid * DIM + k], fW2[k], acc);
        out[tid] = acc;
    }
}

// ---------------------------------------------------------------------------
extern "C" void kernel_launch(void* const* d_in, const int* in_sizes, int n_in,
                              void* d_out, int out_size) {
    const float* x     = (const float*)d_in[0];
    const int*   ei    = (const int*)d_in[1];
    const int*   batch = (const int*)d_in[2];
    const float* W1    = (const float*)d_in[3];
    const float* b1    = (const float*)d_in[4];
    const float* W2    = (const float*)d_in[5];
    const float* b2    = (const float*)d_in[6];
    const float* eps   = (const float*)d_in[7];
    const float* fW1   = (const float*)d_in[8];
    const float* fb1   = (const float*)d_in[9];
    const float* fW2   = (const float*)d_in[10];
    const float* fb2   = (const float*)d_in[11];
    float*       out   = (float*)d_out;

    static bool attr_done = false;
    if (!attr_done) {
        cudaFuncSetAttribute(layer_fused, cudaFuncAttributeMaxDynamicSharedMemorySize, L_SMEM);
        attr_done = true;
    }

    float *h0p, *h1p;
    __nv_bfloat16 *zhp, *zlp, *w1hp, *w1lp, *w2hp, *w2lp;
    cudaGetSymbolAddress((void**)&zhp,  g_zh);
    cudaGetSymbolAddress((void**)&zlp,  g_zl);
    cudaGetSymbolAddress((void**)&h0p,  g_h0);
    cudaGetSymbolAddress((void**)&h1p,  g_h1);
    cudaGetSymbolAddress((void**)&w1hp, g_w1h);
    cudaGetSymbolAddress((void**)&w1lp, g_w1l);
    cudaGetSymbolAddress((void**)&w2hp, g_w2h);
    cudaGetSymbolAddress((void**)&w2lp, g_w2l);
    float* hbufs[2] = {h0p, h1p};

    // Single-launch prologue: all init tasks concurrently
    init_kernel<<<(INIT_TOTAL + 255) / 256, 256>>>(W1, W2);
    fill_slots_kernel<<<(NE + 255) / 256, 256>>>(ei);

    const int tiles = NNP / 128;   // 391
    const float* hin = x;
    for (int l = 0; l < 3; l++) {
        gather_kernel<<<(NN + 7) / 8, 256>>>(hin, eps, l);
        float* hout = hbufs[l & 1];
        int do_pool = (l == 2);
        layer_fused<<<tiles, 512, L_SMEM>>>(
            zhp, zlp,
            w1hp + l * 192 * P1, w1lp + l * 192 * P1, b1 + (size_t)l * H2,
            w2hp + l * 96 * P2, w2lp + l * 96 * P2, b2 + (size_t)l * DIM,
            hout, batch, do_pool);
        hin = hout;
    }

    final_kernel<<<1, 256>>>(fW1, fb1, fW2, fb2, out);
}